// round 14
// baseline (speedup 1.0000x reference)
#include <cuda_runtime.h>
#include <cuda_bf16.h>
#include <cstdint>
#include <math.h>

#define NTOK 384
#define CDIM 128
#define NROWS (NTOK*NTOK)   /* 147456 */
#define EPSV 1e-5f

// Scratch (no cudaMalloc allowed)
__device__ float g_gate[(size_t)NROWS*CDIM];
__device__ float g_tri [(size_t)NROWS*CDIM];           // [c][i*384+j]
__device__ float g_Wt  [5*CDIM*CDIM];                  // tf32-rounded W: Wl,Wgl,Wr,Wgr,Wg
__device__ __nv_bfloat16 g_Lhi[(size_t)CDIM*NROWS];    // [c][i*384+k]
__device__ __nv_bfloat16 g_Llo[(size_t)CDIM*NROWS];
__device__ __nv_bfloat16 g_Rhi[(size_t)CDIM*NROWS];    // [c][j*384+k]
__device__ __nv_bfloat16 g_Rlo[(size_t)CDIM*NROWS];

// fast sigmoid
__device__ __forceinline__ float fsig(float z){
  return __fdividef(1.f, 1.f + __expf(-z));
}

__device__ __forceinline__ uint32_t tf32_rna(float f){
  uint32_t r; asm("cvt.rna.tf32.f32 %0, %1;" : "=r"(r) : "f"(f)); return r;
}
__device__ __forceinline__ uint32_t prmt_(uint32_t a, uint32_t b, uint32_t s){
  uint32_t d; asm("prmt.b32 %0,%1,%2,%3;" : "=r"(d) : "r"(a), "r"(b), "r"(s)); return d;
}
__device__ __forceinline__ uint32_t pack_hilo(float v){
  __nv_bfloat16 h = __float2bfloat16(v);
  float rem = v - __bfloat162float(h);
  __nv_bfloat16 l = __float2bfloat16(rem);
  uint16_t hb = *reinterpret_cast<uint16_t*>(&h);
  uint16_t lb = *reinterpret_cast<uint16_t*>(&l);
  return (uint32_t)hb | ((uint32_t)lb << 16);
}
__device__ __forceinline__ uint32_t smem_u32(const void* p){
  uint32_t a;
  asm("{ .reg .u64 t; cvta.to.shared.u64 t, %1; cvt.u32.u64 %0, t; }" : "=r"(a) : "l"(p));
  return a;
}
__device__ __forceinline__ void cp16(uint32_t dst_smem, const void* src){
  asm volatile("cp.async.ca.shared.global [%0], [%1], 16;" :: "r"(dst_smem), "l"(src));
}
__device__ __forceinline__ void cp_commit(){
  asm volatile("cp.async.commit_group;");
}
template<int N>
__device__ __forceinline__ void cp_wait(){
  asm volatile("cp.async.wait_group %0;" :: "n"(N));
}
__device__ __forceinline__ void cp_commit_wait(){
  asm volatile("cp.async.commit_group;");
  asm volatile("cp.async.wait_group 0;");
}
// ldmatrix x4 (sm_75 base ISA)
__device__ __forceinline__ void ldm4(uint32_t* r, uint32_t addr){
  asm volatile("ldmatrix.sync.aligned.m8n8.x4.shared.b16 {%0,%1,%2,%3}, [%4];"
    : "=r"(r[0]), "=r"(r[1]), "=r"(r[2]), "=r"(r[3]) : "r"(addr));
}

// m16n8k8 tf32 mma
__device__ __forceinline__ void mma_tf32(float& d0, float& d1, float& d2, float& d3,
                                         uint32_t a0, uint32_t a1, uint32_t a2, uint32_t a3,
                                         uint32_t b0, uint32_t b1){
  asm volatile(
    "mma.sync.aligned.m16n8k8.row.col.f32.tf32.tf32.f32 "
    "{%0,%1,%2,%3}, {%4,%5,%6,%7}, {%8,%9}, {%0,%1,%2,%3};"
    : "+f"(d0), "+f"(d1), "+f"(d2), "+f"(d3)
    : "r"(a0), "r"(a1), "r"(a2), "r"(a3), "r"(b0), "r"(b1));
}
// m16n8k16 bf16 mma
__device__ __forceinline__ void mma_bf16(float* d, const uint32_t* a, uint32_t b0, uint32_t b1){
  asm volatile(
    "mma.sync.aligned.m16n8k16.row.col.f32.bf16.bf16.f32 "
    "{%0,%1,%2,%3}, {%4,%5,%6,%7}, {%8,%9}, {%0,%1,%2,%3};"
    : "+f"(d[0]), "+f"(d[1]), "+f"(d[2]), "+f"(d[3])
    : "r"(a[0]), "r"(a[1]), "r"(a[2]), "r"(a[3]), "r"(b0), "r"(b1));
}

#define LDX 132
#define LDW 136
#define LDE2 68

// ---- W pre-round kernel: 5 matrices fp32 -> tf32-rounded fp32 ----
__global__ __launch_bounds__(256) void wcvt_kernel(
    const float* __restrict__ a, const float* __restrict__ b, const float* __restrict__ c,
    const float* __restrict__ d, const float* __restrict__ e, float* __restrict__ o){
  int i = blockIdx.x*256 + threadIdx.x;    // grid 64 -> i < 16384
  o[i          ] = __uint_as_float(tf32_rna(a[i]));
  o[i + 16384  ] = __uint_as_float(tf32_rna(b[i]));
  o[i + 32768  ] = __uint_as_float(tf32_rna(c[i]));
  o[i + 49152  ] = __uint_as_float(tf32_rna(d[i]));
  o[i + 65536  ] = __uint_as_float(tf32_rna(e[i]));
}

// ================= fused LN + 5 projections (64-row tiles, 2 CTAs/SM) =================
#define PXS_WORDS (64*LDX)        /* 8448 */
#define WCH_WORDS (32*LDW)        /* 4352 */
#define PROJ_SMEM ((PXS_WORDS + 4*WCH_WORDS)*4)   /* 103424 B */

// K-chunk mainloop segment: kcs [ch*4, ch*4+4)
__device__ __forceinline__ void gemm_seg(const uint32_t* __restrict__ xs,
                                         const uint32_t* __restrict__ w1,
                                         const uint32_t* __restrict__ w2,
                                         int ch, int wm, int wn, int gid, int tig,
                                         float acc1[2][4][4], float acc2[2][4][4],
                                         bool dual){
  const uint32_t* xa  = xs + (wm*32 + gid)*LDX + tig + ch*32;
  const uint32_t* wb1 = w1 + tig*LDW + wn*32 + gid;
  const uint32_t* wb2 = w2 + tig*LDW + wn*32 + gid;
  #pragma unroll
  for (int kcl=0; kcl<4; kcl++){
    uint32_t a[2][4];
    #pragma unroll
    for (int t=0;t<2;t++){
      const uint32_t* p = xa + t*16*LDX + kcl*8;
      a[t][0] = p[0];
      a[t][1] = p[8*LDX];
      a[t][2] = p[4];
      a[t][3] = p[8*LDX + 4];
    }
    #pragma unroll
    for (int u=0;u<4;u++){
      const uint32_t* q1 = wb1 + kcl*8*LDW + u*8;
      uint32_t b10 = q1[0], b11 = q1[4*LDW];
      #pragma unroll
      for (int t=0;t<2;t++)
        mma_tf32(acc1[t][u][0],acc1[t][u][1],acc1[t][u][2],acc1[t][u][3],
                 a[t][0],a[t][1],a[t][2],a[t][3], b10,b11);
      if (dual){
        const uint32_t* q2 = wb2 + kcl*8*LDW + u*8;
        uint32_t b20 = q2[0], b21 = q2[4*LDW];
        #pragma unroll
        for (int t=0;t<2;t++)
          mma_tf32(acc2[t][u][0],acc2[t][u][1],acc2[t][u][2],acc2[t][u][3],
                   a[t][0],a[t][1],a[t][2],a[t][3], b20,b21);
      }
    }
  }
}

__device__ __forceinline__ void compute_pk64(const float acc1[2][4][4], const float acc2[2][4][4],
    const float* __restrict__ mask, const float* __restrict__ bb1, const float* __restrict__ bb2,
    int row0, int wm, int wn, int gid, int tig, uint32_t pk[32]){
  #pragma unroll
  for (int t=0;t<2;t++){
    int rA = wm*32 + t*16 + gid;
    int rB = rA + 8;
    float mvA = mask[row0 + rA], mvB = mask[row0 + rB];
    #pragma unroll
    for (int u=0;u<4;u++){
      int colb = wn*32 + u*8 + 2*tig;
      float2 b1v = *reinterpret_cast<const float2*>(&bb1[colb]);
      float2 b2v = *reinterpret_cast<const float2*>(&bb2[colb]);
      float v0 = mvA*(acc1[t][u][0]+b1v.x)*fsig(acc2[t][u][0]+b2v.x);
      float v1 = mvA*(acc1[t][u][1]+b1v.y)*fsig(acc2[t][u][1]+b2v.y);
      float v2 = mvB*(acc1[t][u][2]+b1v.x)*fsig(acc2[t][u][2]+b2v.x);
      float v3 = mvB*(acc1[t][u][3]+b1v.y)*fsig(acc2[t][u][3]+b2v.y);
      pk[t*16+u*4+0] = pack_hilo(v0);
      pk[t*16+u*4+1] = pack_hilo(v1);
      pk[t*16+u*4+2] = pack_hilo(v2);
      pk[t*16+u*4+3] = pack_hilo(v3);
    }
  }
}

// 64-row single-pass epilogue through ebuf (stride 68), 2 syncs
__device__ __forceinline__ void epi_store64(const uint32_t pk[32], uint32_t* __restrict__ ebuf,
    __nv_bfloat16* __restrict__ ghi, __nv_bfloat16* __restrict__ glo,
    int row0, int tid, int wm, int wn, int gid, int tig){
  #pragma unroll
  for (int t=0;t<2;t++){
    int rA = wm*32 + t*16 + gid;
    int rB = rA + 8;
    #pragma unroll
    for (int u=0;u<4;u++){
      int cl = wn*32 + u*8 + 2*tig;
      ebuf[ cl   *LDE2 + rA] = pk[t*16+u*4+0];
      ebuf[(cl+1)*LDE2 + rA] = pk[t*16+u*4+1];
      ebuf[ cl   *LDE2 + rB] = pk[t*16+u*4+2];
      ebuf[(cl+1)*LDE2 + rB] = pk[t*16+u*4+3];
    }
  }
  __syncthreads();
  {
    int cl   = tid >> 1;      // 0..127
    int half = tid & 1;       // rows half*32 .. +31
    #pragma unroll
    for (int h=0; h<8; h++){
      int r4 = half*32 + h*4;
      uint4 w = *reinterpret_cast<const uint4*>(&ebuf[cl*LDE2 + r4]);
      uint32_t hi01 = prmt_(w.x, w.y, 0x5410u);
      uint32_t hi23 = prmt_(w.z, w.w, 0x5410u);
      uint32_t lo01 = prmt_(w.x, w.y, 0x7632u);
      uint32_t lo23 = prmt_(w.z, w.w, 0x7632u);
      size_t base = (size_t)cl*NROWS + row0 + r4;
      *reinterpret_cast<uint2*>(&ghi[base]) = make_uint2(hi01, hi23);
      *reinterpret_cast<uint2*>(&glo[base]) = make_uint2(lo01, lo23);
    }
  }
  __syncthreads();
}

__global__ __launch_bounds__(256, 2) void proj_all_kernel(
    const float* __restrict__ act, const float* __restrict__ lng, const float* __restrict__ lnb,
    const float* __restrict__ mask,
    const float* __restrict__ bl,  const float* __restrict__ bgl,
    const float* __restrict__ br,  const float* __restrict__ bgr,
    const float* __restrict__ bg,
    __nv_bfloat16* __restrict__ gLh, __nv_bfloat16* __restrict__ gLl,
    __nv_bfloat16* __restrict__ gRh, __nv_bfloat16* __restrict__ gRl,
    float* __restrict__ gate){
  extern __shared__ uint32_t sm[];
  uint32_t* xs = sm;
  uint32_t* wb[4] = { sm + PXS_WORDS,
                      sm + PXS_WORDS + WCH_WORDS,
                      sm + PXS_WORDS + 2*WCH_WORDS,
                      sm + PXS_WORDS + 3*WCH_WORDS };
  uint32_t  swb = smem_u32(wb[0]);       // byte base of chunk buffers
  int tid  = threadIdx.x;
  int row0 = blockIdx.x * 64;
  int kv   = tid & 31;

  // ---- stage act tile: LDG + in-register LN + tf32 STS ----
  {
    float4 g4 = *reinterpret_cast<const float4*>(&lng[kv*4]);
    float4 b4 = *reinterpret_cast<const float4*>(&lnb[kv*4]);
    #pragma unroll
    for (int it=0; it<8; ++it){
      int r = (tid>>5) + it*8;
      float4 v = *reinterpret_cast<const float4*>(&act[(size_t)(row0+r)*CDIM + kv*4]);
      float s  = v.x + v.y + v.z + v.w;
      float s2 = v.x*v.x + v.y*v.y + v.z*v.z + v.w*v.w;
      #pragma unroll
      for (int off=16; off>0; off>>=1){
        s  += __shfl_xor_sync(0xffffffffu, s,  off);
        s2 += __shfl_xor_sync(0xffffffffu, s2, off);
      }
      float mu = s * (1.f/128.f);
      float rs = rsqrtf(s2*(1.f/128.f) - mu*mu + EPSV);
      uint4 t;
      t.x = tf32_rna((v.x-mu)*rs*g4.x + b4.x);
      t.y = tf32_rna((v.y-mu)*rs*g4.y + b4.y);
      t.z = tf32_rna((v.z-mu)*rs*g4.z + b4.z);
      t.w = tf32_rna((v.w-mu)*rs*g4.w + b4.w);
      *reinterpret_cast<uint4*>(&xs[r*LDX + kv*4]) = t;
    }
  }

  int lane = tid&31, wid = tid>>5;
  int wm = wid>>2, wn = wid&3;      // 2 x 4 warp grid
  int gid = lane>>2, tig = lane&3;

  const float* Wt = g_Wt;           // [Wl | Wgl | Wr | Wgr | Wg] x 16384

  // cp.async one 32-k chunk of one or two pre-rounded W matrices into buffer pair
  auto issue = [&](int m1, int m2, int ch, int pair, bool dual){
    uint32_t d1 = swb + (uint32_t)(pair*2*WCH_WORDS*4);
    uint32_t d2 = d1 + (uint32_t)(WCH_WORDS*4);
    #pragma unroll
    for (int it=0; it<4; ++it){
      int slot = tid + it*256;
      int r  = slot >> 5;           // 0..31
      int kq = slot & 31;
      uint32_t off = (uint32_t)((r*LDW + kq*4)*4);
      cp16(d1 + off, Wt + m1*16384 + (ch*32+r)*128 + kq*4);
      if (dual) cp16(d2 + off, Wt + m2*16384 + (ch*32+r)*128 + kq*4);
    }
    cp_commit();
  };

  float acc1[2][4][4], acc2[2][4][4];
  uint32_t pk[32];

  auto run_gemm = [&](int m1, int m2, bool dual){
    #pragma unroll
    for (int t=0;t<2;t++)
      #pragma unroll
      for (int u=0;u<4;u++)
        #pragma unroll
        for (int r=0;r<4;r++){ acc1[t][u][r]=0.f; acc2[t][u][r]=0.f; }
    issue(m1, m2, 0, 0, dual);
    #pragma unroll
    for (int ch=0; ch<4; ch++){
      if (ch<3){ issue(m1, m2, ch+1, (ch+1)&1, dual); cp_wait<1>(); }
      else     { cp_wait<0>(); }
      __syncthreads();
      int p = (ch&1)*2;
      gemm_seg(xs, wb[p], wb[p+1], ch, wm, wn, gid, tig, acc1, acc2, dual);
      __syncthreads();
    }
  };

  // GEMM 1: left
  run_gemm(0, 1, true);
  compute_pk64(acc1, acc2, mask, bl, bgl, row0, wm, wn, gid, tig, pk);
  epi_store64(pk, wb[0], gLh, gLl, row0, tid, wm, wn, gid, tig);

  // GEMM 2: right
  run_gemm(2, 3, true);
  compute_pk64(acc1, acc2, mask, br, bgr, row0, wm, wn, gid, tig, pk);
  epi_store64(pk, wb[0], gRh, gRl, row0, tid, wm, wn, gid, tig);

  // GEMM 3: gate
  run_gemm(4, 4, false);
  #pragma unroll
  for (int t=0;t<2;t++){
    int rowA = row0 + wm*32 + t*16 + gid;
    int rowB = rowA + 8;
    #pragma unroll
    for (int u=0;u<4;u++){
      int colb = wn*32 + u*8 + 2*tig;
      float b0 = bg[colb], b1 = bg[colb+1];
      float2 oA, oB;
      oA.x = fsig(acc1[t][u][0]+b0);
      oA.y = fsig(acc1[t][u][1]+b1);
      oB.x = fsig(acc1[t][u][2]+b0);
      oB.y = fsig(acc1[t][u][3]+b1);
      *reinterpret_cast<float2*>(&gate[(size_t)rowA*CDIM + colb]) = oA;
      *reinterpret_cast<float2*>(&gate[(size_t)rowB*CDIM + colb]) = oB;
    }
  }
}

// ============== Stage 3: per-channel GEMM via bf16-split mma + ldmatrix ==============
#define TRI_LDS 72
#define TRI_SMEM ((64*TRI_LDS*2 + 128*TRI_LDS*2)*2)
__global__ __launch_bounds__(256, 2) void tri_kernel(){
  extern __shared__ __nv_bfloat16 smb[];
  __nv_bfloat16* Lhi = smb;
  __nv_bfloat16* Llo = smb + 64*TRI_LDS;
  __nv_bfloat16* Rhi = smb + 2*64*TRI_LDS;
  __nv_bfloat16* Rlo = Rhi + 128*TRI_LDS;
  uint32_t sLhi = smem_u32(Lhi);
  uint32_t sLlo = smem_u32(Llo);
  uint32_t sRhi = smem_u32(Rhi);
  uint32_t sRlo = smem_u32(Rlo);
  int tid = threadIdx.x;
  int c  = blockIdx.z;
  int i0 = blockIdx.x * 64;
  int j0 = blockIdx.y * 128;
  const __nv_bfloat16* gLh = g_Lhi + (size_t)c*NROWS;
  const __nv_bfloat16* gLl = g_Llo + (size_t)c*NROWS;
  const __nv_bfloat16* gRh = g_Rhi + (size_t)c*NROWS;
  const __nv_bfloat16* gRl = g_Rlo + (size_t)c*NROWS;

  int lane = tid&31, wid = tid>>5;
  int wm = wid>>2, wn = wid&3;
  int gid = lane>>2, tig = lane&3;

  int sr = tid>>3, sseg = tid&7;

  uint32_t offA0 = (uint32_t)(((wm*32 + (lane&15))*TRI_LDS + ((lane>>4)<<3))*2);
  uint32_t offA1 = offA0 + (uint32_t)(16*TRI_LDS*2);
  uint32_t offB0 = (uint32_t)(((wn*32 + (lane&7) + ((lane>>4)<<3))*TRI_LDS + (((lane>>3)&1)<<3))*2);
  uint32_t offB2 = offB0 + (uint32_t)(16*TRI_LDS*2);

  float acc[2][4][4];
  #pragma unroll
  for (int t=0;t<2;t++)
    #pragma unroll
    for (int u=0;u<4;u++)
      #pragma unroll
      for (int r=0;r<4;r++) acc[t][u][r]=0.f;

  for (int kc=0; kc<NTOK; kc+=64){
    __syncthreads();
    #pragma unroll
    for (int it=0; it<2; it++){
      int r = sr + it*32;
      size_t go = (size_t)(i0+r)*NTOK + kc + sseg*8;
      uint32_t so = (uint32_t)(r*TRI_LDS + sseg*8)*2;
      cp16(sLhi + so, &gLh[go]);
      cp16(sLlo + so, &gLl[go]);
    }
    #pragma unroll
    for (int it=0; it<4; it++){
      int r = sr + it*32;
      size_t go = (size_t)(j0+r)*NTOK + kc + sseg*8;
      uint32_t so = (uint32_t)(r*TRI_LDS + sseg*8)*2;
      cp16(sRhi + so, &gRh[go]);
      cp16(sRlo + so, &gRl[go]);
    }
    cp_commit_wait();
    __syncthreads();

    #pragma unroll
    for (int ks=0; ks<4; ks++){
      uint32_t kso = (uint32_t)(ks*32);
      uint32_t ah[2][4], al[2][4];
      ldm4(ah[0], sLhi + offA0 + kso);
      ldm4(ah[1], sLhi + offA1 + kso);
      ldm4(al[0], sLlo + offA0 + kso);
      ldm4(al[1], sLlo + offA1 + kso);
      uint32_t bh01[4], bh23[4], bl01[4], bl23[4];
      ldm4(bh01, sRhi + offB0 + kso);
      ldm4(bh23, sRhi + offB2 + kso);
      ldm4(bl01, sRlo + offB0 + kso);
      ldm4(bl23, sRlo + offB2 + kso);
      const uint32_t* bhp[4] = { &bh01[0], &bh01[2], &bh23[0], &bh23[2] };
      const uint32_t* blp[4] = { &bl01[0], &bl01[2], &bl23[0], &bl23[2] };
      #pragma unroll
      for (int u=0;u<4;u++){
        uint32_t bh0 = bhp[u][0], bh1 = bhp[u][1];
        uint32_t bl0 = blp[u][0], bl1 = blp[u][1];
        #pragma unroll
        for (int t=0;t<2;t++){
          mma_bf16(acc[t][u], ah[t], bh0, bh1);
          mma_bf16(acc[t][u], ah[t], bl0, bl1);
          mma_bf16(acc[t][u], al[t], bh0, bh1);
        }
      }
    }
  }

  float* To = g_tri + (size_t)c*NROWS;
  #pragma unroll
  for (int t=0;t<2;t++){
    int iA = i0 + wm*32 + t*16 + gid;
    int iB = iA + 8;
    #pragma unroll
    for (int u=0;u<4;u++){
      int j = j0 + wn*32 + u*8 + 2*tig;
      float2 vA = {acc[t][u][0], acc[t][u][1]};
      float2 vB = {acc[t][u][2], acc[t][u][3]};
      *reinterpret_cast<float2*>(&To[(size_t)iA*NTOK + j]) = vA;
      *reinterpret_cast<float2*>(&To[(size_t)iB*NTOK + j]) = vB;
    }
  }
}

// ============== Stage 4: LN(tri) @ Wo + bo, * gate (tf32 mma) ==============
// full-K gemm (for final only)
#define XS_WORDS (128*LDX)
#define W_WORDS  (128*LDW)
__device__ __forceinline__ void gemm_full(const uint32_t* __restrict__ xs,
                                          const uint32_t* __restrict__ w1,
                                          int wm, int wn, int gid, int tig,
                                          float acc1[2][4][4]){
  const uint32_t* xa  = xs + (wm*32 + gid)*LDX + tig;
  const uint32_t* wb1 = w1 + tig*LDW + wn*32 + gid;
  #pragma unroll
  for (int kc=0; kc<16; kc++){
    uint32_t a[2][4];
    #pragma unroll
    for (int t=0;t<2;t++){
      const uint32_t* p = xa + t*16*LDX + kc*8;
      a[t][0] = p[0];
      a[t][1] = p[8*LDX];
      a[t][2] = p[4];
      a[t][3] = p[8*LDX + 4];
    }
    #pragma unroll
    for (int u=0;u<4;u++){
      const uint32_t* q1 = wb1 + kc*8*LDW + u*8;
      uint32_t b10 = q1[0], b11 = q1[4*LDW];
      #pragma unroll
      for (int t=0;t<2;t++)
        mma_tf32(acc1[t][u][0],acc1[t][u][1],acc1[t][u][2],acc1[t][u][3],
                 a[t][0],a[t][1],a[t][2],a[t][3], b10,b11);
    }
  }
}

#define LDT 129
#define FINAL_SMEM ((128*LDT + XS_WORDS + W_WORDS)*4)
__global__ __launch_bounds__(512) void final_kernel(const float* __restrict__ cg,
                                                    const float* __restrict__ cb,
                                                    const float* __restrict__ Wo,
                                                    const float* __restrict__ bo,
                                                    float* __restrict__ out){
  extern __shared__ uint32_t sm[];
  float*    T  = reinterpret_cast<float*>(sm);
  uint32_t* xs = sm + 128*LDT;
  uint32_t* w  = xs + XS_WORDS;
  __shared__ float p1[4][128], p2[4][128], mu_s[128], rs_s[128];
  int tid  = threadIdx.x;
  int row0 = blockIdx.x * 128;

  #pragma unroll
  for (int it=0; it<8; ++it){
    int slot = tid + it*512;
    int cch = slot >> 5;
    int v4  = slot & 31;
    float4 v = *reinterpret_cast<const float4*>(&g_tri[(size_t)cch*NROWS + row0 + v4*4]);
    T[cch*LDT + v4*4 + 0] = v.x;
    T[cch*LDT + v4*4 + 1] = v.y;
    T[cch*LDT + v4*4 + 2] = v.z;
    T[cch*LDT + v4*4 + 3] = v.w;
    v = *reinterpret_cast<const float4*>(&Wo[cch*CDIM + v4*4]);
    uint4 t; t.x=tf32_rna(v.x); t.y=tf32_rna(v.y); t.z=tf32_rna(v.z); t.w=tf32_rna(v.w);
    *reinterpret_cast<uint4*>(&w[cch*LDW + v4*4]) = t;
  }
  __syncthreads();

  {
    int ij = tid & 127, pp = tid >> 7;
    float s=0.f, s2=0.f;
    #pragma unroll
    for (int k=0;k<32;k++){
      float v = T[(pp*32+k)*LDT + ij];
      s += v; s2 += v*v;
    }
    p1[pp][ij] = s; p2[pp][ij] = s2;
  }
  __syncthreads();
  if (tid < 128){
    float s  = p1[0][tid]+p1[1][tid]+p1[2][tid]+p1[3][tid];
    float s2 = p2[0][tid]+p2[1][tid]+p2[2][tid]+p2[3][tid];
    float mu = s*(1.f/128.f);
    mu_s[tid] = mu;
    rs_s[tid] = rsqrtf(s2*(1.f/128.f) - mu*mu + EPSV);
  }
  __syncthreads();

  #pragma unroll
  for (int it=0; it<8; ++it){
    int slot = tid + it*512;
    int r  = slot & 127;
    int cq = slot >> 7;
    float mu = mu_s[r], rs = rs_s[r];
    uint4 t;
    {
      int c0 = cq*4;
      float v0 = (T[(c0+0)*LDT + r]-mu)*rs*cg[c0+0] + cb[c0+0];
      float v1 = (T[(c0+1)*LDT + r]-mu)*rs*cg[c0+1] + cb[c0+1];
      float v2 = (T[(c0+2)*LDT + r]-mu)*rs*cg[c0+2] + cb[c0+2];
      float v3 = (T[(c0+3)*LDT + r]-mu)*rs*cg[c0+3] + cb[c0+3];
      t.x=tf32_rna(v0); t.y=tf32_rna(v1); t.z=tf32_rna(v2); t.w=tf32_rna(v3);
    }
    *reinterpret_cast<uint4*>(&xs[r*LDX + cq*4]) = t;
  }
  __syncthreads();

  int lane = tid&31, wid = tid>>5;
  int wm = wid>>2, wn = wid&3;
  int gid = lane>>2, tig = lane&3;

  float acc[2][4][4];
  #pragma unroll
  for (int t=0;t<2;t++)
    #pragma unroll
    for (int u=0;u<4;u++)
      #pragma unroll
      for (int r=0;r<4;r++) acc[t][u][r]=0.f;

  gemm_full(xs, w, wm, wn, gid, tig, acc);

  #pragma unroll
  for (int t=0;t<2;t++){
    int rowA = row0 + wm*32 + t*16 + gid;
    int rowB = rowA + 8;
    #pragma unroll
    for (int u=0;u<4;u++){
      int colb = wn*32 + u*8 + 2*tig;
      float bo0 = bo[colb], bo1 = bo[colb+1];
      float2 gA = *reinterpret_cast<const float2*>(&g_gate[(size_t)rowA*CDIM + colb]);
      float2 gB = *reinterpret_cast<const float2*>(&g_gate[(size_t)rowB*CDIM + colb]);
      float2 oA, oB;
      oA.x = (acc[t][u][0]+bo0)*gA.x;
      oA.y = (acc[t][u][1]+bo1)*gA.y;
      oB.x = (acc[t][u][2]+bo0)*gB.x;
      oB.y = (acc[t][u][3]+bo1)*gB.y;
      *reinterpret_cast<float2*>(&out[(size_t)rowA*CDIM + colb]) = oA;
      *reinterpret_cast<float2*>(&out[(size_t)rowB*CDIM + colb]) = oB;
    }
  }
}

extern "C" void kernel_launch(void* const* d_in, const int* in_sizes, int n_in,
                              void* d_out, int out_size) {
  const float* act  = (const float*)d_in[0];
  const float* mask = (const float*)d_in[1];
  const float* ln_g = (const float*)d_in[2];
  const float* ln_b = (const float*)d_in[3];
  const float* Wl   = (const float*)d_in[4];
  const float* bl   = (const float*)d_in[5];
  const float* Wr   = (const float*)d_in[6];
  const float* br   = (const float*)d_in[7];
  const float* Wgl  = (const float*)d_in[8];
  const float* bgl  = (const float*)d_in[9];
  const float* Wgr  = (const float*)d_in[10];
  const float* bgr  = (const float*)d_in[11];
  const float* cg   = (const float*)d_in[12];
  const float* cb   = (const float*)d_in[13];
  const float* Wo   = (const float*)d_in[14];
  const float* bo   = (const float*)d_in[15];
  const float* Wg   = (const float*)d_in[16];
  const float* bg   = (const float*)d_in[17];
  float* out = (float*)d_out;

  __nv_bfloat16 *dLh=nullptr, *dLl=nullptr, *dRh=nullptr, *dRl=nullptr;
  float *dGate=nullptr, *dWt=nullptr;
  cudaGetSymbolAddress((void**)&dLh, g_Lhi);
  cudaGetSymbolAddress((void**)&dLl, g_Llo);
  cudaGetSymbolAddress((void**)&dRh, g_Rhi);
  cudaGetSymbolAddress((void**)&dRl, g_Rlo);
  cudaGetSymbolAddress((void**)&dGate, g_gate);
  cudaGetSymbolAddress((void**)&dWt, g_Wt);

  cudaFuncSetAttribute(proj_all_kernel, cudaFuncAttributeMaxDynamicSharedMemorySize, PROJ_SMEM);
  cudaFuncSetAttribute(tri_kernel,      cudaFuncAttributeMaxDynamicSharedMemorySize, TRI_SMEM);
  cudaFuncSetAttribute(final_kernel,    cudaFuncAttributeMaxDynamicSharedMemorySize, FINAL_SMEM);

  wcvt_kernel<<<64, 256>>>(Wl, Wgl, Wr, Wgr, Wg, dWt);
  proj_all_kernel<<<NROWS/64, 256, PROJ_SMEM>>>(act, ln_g, ln_b, mask,
      bl, bgl, br, bgr, bg,
      dLh, dLl, dRh, dRl, dGate);
  tri_kernel<<<dim3(NTOK/64, NTOK/128, CDIM), 256, TRI_SMEM>>>();
  final_kernel<<<NROWS/128, 512, FINAL_SMEM>>>(cg, cb, Wo, bo, out);
}

// round 15
// speedup vs baseline: 1.6564x; 1.6564x over previous
#include <cuda_runtime.h>
#include <cuda_bf16.h>
#include <cstdint>
#include <math.h>

#define NTOK 384
#define CDIM 128
#define NROWS (NTOK*NTOK)   /* 147456 */
#define EPSV 1e-5f

// Scratch (no cudaMalloc allowed)
__device__ float g_gate[(size_t)NROWS*CDIM];
__device__ float g_tri [(size_t)NROWS*CDIM];           // [c][i*384+j]
__device__ __nv_bfloat16 g_Lhi[(size_t)CDIM*NROWS];    // [c][i*384+k]
__device__ __nv_bfloat16 g_Llo[(size_t)CDIM*NROWS];
__device__ __nv_bfloat16 g_Rhi[(size_t)CDIM*NROWS];    // [c][j*384+k]
__device__ __nv_bfloat16 g_Rlo[(size_t)CDIM*NROWS];

// fast sigmoid: MUFU.EX2 + MUFU.RCP path (rel err ~2^-21, tolerance 1e-3)
__device__ __forceinline__ float fsig(float z){
  return __fdividef(1.f, 1.f + __expf(-z));
}

__device__ __forceinline__ uint32_t tf32_rna(float f){
  uint32_t r; asm("cvt.rna.tf32.f32 %0, %1;" : "=r"(r) : "f"(f)); return r;
}
__device__ __forceinline__ uint32_t prmt_(uint32_t a, uint32_t b, uint32_t s){
  uint32_t d; asm("prmt.b32 %0,%1,%2,%3;" : "=r"(d) : "r"(a), "r"(b), "r"(s)); return d;
}
__device__ __forceinline__ uint32_t pack_hilo(float v){
  __nv_bfloat16 h = __float2bfloat16(v);
  float rem = v - __bfloat162float(h);
  __nv_bfloat16 l = __float2bfloat16(rem);
  uint16_t hb = *reinterpret_cast<uint16_t*>(&h);
  uint16_t lb = *reinterpret_cast<uint16_t*>(&l);
  return (uint32_t)hb | ((uint32_t)lb << 16);
}
__device__ __forceinline__ uint32_t smem_u32(const void* p){
  uint32_t a;
  asm("{ .reg .u64 t; cvta.to.shared.u64 t, %1; cvt.u32.u64 %0, t; }" : "=r"(a) : "l"(p));
  return a;
}
__device__ __forceinline__ void cp16(uint32_t dst_smem, const void* src){
  asm volatile("cp.async.ca.shared.global [%0], [%1], 16;" :: "r"(dst_smem), "l"(src));
}
__device__ __forceinline__ void cp_commit_wait(){
  asm volatile("cp.async.commit_group;");
  asm volatile("cp.async.wait_group 0;");
}
// ldmatrix x4 (sm_75 base ISA)
__device__ __forceinline__ void ldm4(uint32_t* r, uint32_t addr){
  asm volatile("ldmatrix.sync.aligned.m8n8.x4.shared.b16 {%0,%1,%2,%3}, [%4];"
    : "=r"(r[0]), "=r"(r[1]), "=r"(r[2]), "=r"(r[3]) : "r"(addr));
}

// m16n8k8 tf32 mma (sm_80 base ISA)
__device__ __forceinline__ void mma_tf32(float& d0, float& d1, float& d2, float& d3,
                                         uint32_t a0, uint32_t a1, uint32_t a2, uint32_t a3,
                                         uint32_t b0, uint32_t b1){
  asm volatile(
    "mma.sync.aligned.m16n8k8.row.col.f32.tf32.tf32.f32 "
    "{%0,%1,%2,%3}, {%4,%5,%6,%7}, {%8,%9}, {%0,%1,%2,%3};"
    : "+f"(d0), "+f"(d1), "+f"(d2), "+f"(d3)
    : "r"(a0), "r"(a1), "r"(a2), "r"(a3), "r"(b0), "r"(b1));
}
// m16n8k16 bf16 mma (sm_80 base ISA)
__device__ __forceinline__ void mma_bf16(float* d, const uint32_t* a, uint32_t b0, uint32_t b1){
  asm volatile(
    "mma.sync.aligned.m16n8k16.row.col.f32.bf16.bf16.f32 "
    "{%0,%1,%2,%3}, {%4,%5,%6,%7}, {%8,%9}, {%0,%1,%2,%3};"
    : "+f"(d[0]), "+f"(d[1]), "+f"(d[2]), "+f"(d[3])
    : "r"(a[0]), "r"(a[1]), "r"(a[2]), "r"(a[3]), "r"(b0), "r"(b1));
}

// ================= fused LN + 5 projections (R13 proven config) =================
#define LDX 132
#define LDW 136
#define LDE 132
#define XS_WORDS (128*LDX)
#define W_WORDS  (128*LDW)
#define PROJALL_SMEM ((XS_WORDS + 2*W_WORDS)*4)

__device__ __forceinline__ void gemm_pair(const uint32_t* __restrict__ xs,
                                          const uint32_t* __restrict__ w1,
                                          const uint32_t* __restrict__ w2,
                                          int wm, int wn, int gid, int tig,
                                          float acc1[2][4][4], float acc2[2][4][4],
                                          bool dual){
  const uint32_t* xa  = xs + (wm*32 + gid)*LDX + tig;
  const uint32_t* wb1 = w1 + tig*LDW + wn*32 + gid;
  const uint32_t* wb2 = w2 + tig*LDW + wn*32 + gid;
  #pragma unroll
  for (int kc=0; kc<16; kc++){
    uint32_t a[2][4];
    #pragma unroll
    for (int t=0;t<2;t++){
      const uint32_t* p = xa + t*16*LDX + kc*8;
      a[t][0] = p[0];
      a[t][1] = p[8*LDX];
      a[t][2] = p[4];
      a[t][3] = p[8*LDX + 4];
    }
    #pragma unroll
    for (int u=0;u<4;u++){
      const uint32_t* q1 = wb1 + kc*8*LDW + u*8;
      uint32_t b10 = q1[0], b11 = q1[4*LDW];
      #pragma unroll
      for (int t=0;t<2;t++)
        mma_tf32(acc1[t][u][0],acc1[t][u][1],acc1[t][u][2],acc1[t][u][3],
                 a[t][0],a[t][1],a[t][2],a[t][3], b10,b11);
      if (dual){
        const uint32_t* q2 = wb2 + kc*8*LDW + u*8;
        uint32_t b20 = q2[0], b21 = q2[4*LDW];
        #pragma unroll
        for (int t=0;t<2;t++)
          mma_tf32(acc2[t][u][0],acc2[t][u][1],acc2[t][u][2],acc2[t][u][3],
                   a[t][0],a[t][1],a[t][2],a[t][3], b20,b21);
      }
    }
  }
}

__device__ __forceinline__ void ldgW(const float* __restrict__ W, int tid, uint4 w[8]){
  #pragma unroll
  for (int it=0; it<8; ++it){
    int slot = tid + it*512;
    int r  = slot >> 5;
    int kv = slot & 31;
    w[it] = *reinterpret_cast<const uint4*>(&W[r*CDIM + kv*4]);
  }
}
__device__ __forceinline__ void stsW(const uint4 w[8], int tid, uint32_t* __restrict__ dst){
  #pragma unroll
  for (int it=0; it<8; ++it){
    int slot = tid + it*512;
    int r  = slot >> 5;
    int kv = slot & 31;
    float4 v = *reinterpret_cast<const float4*>(&w[it]);
    uint4 t; t.x=tf32_rna(v.x); t.y=tf32_rna(v.y); t.z=tf32_rna(v.z); t.w=tf32_rna(v.w);
    *reinterpret_cast<uint4*>(&dst[r*LDW + kv*4]) = t;
  }
}

__device__ __forceinline__ void compute_pk(const float acc1[2][4][4], const float acc2[2][4][4],
    const float* __restrict__ mask, const float* __restrict__ bb1, const float* __restrict__ bb2,
    int row0, int wm, int wn, int gid, int tig, uint32_t pk[32]){
  #pragma unroll
  for (int t=0;t<2;t++){
    int rA = wm*32 + t*16 + gid;
    int rB = rA + 8;
    float mvA = mask[row0 + rA], mvB = mask[row0 + rB];
    #pragma unroll
    for (int u=0;u<4;u++){
      int colb = wn*32 + u*8 + 2*tig;
      float2 b1v = *reinterpret_cast<const float2*>(&bb1[colb]);
      float2 b2v = *reinterpret_cast<const float2*>(&bb2[colb]);
      float v0 = mvA*(acc1[t][u][0]+b1v.x)*fsig(acc2[t][u][0]+b2v.x);
      float v1 = mvA*(acc1[t][u][1]+b1v.y)*fsig(acc2[t][u][1]+b2v.y);
      float v2 = mvB*(acc1[t][u][2]+b1v.x)*fsig(acc2[t][u][2]+b2v.x);
      float v3 = mvB*(acc1[t][u][3]+b1v.y)*fsig(acc2[t][u][3]+b2v.y);
      pk[t*16+u*4+0] = pack_hilo(v0);
      pk[t*16+u*4+1] = pack_hilo(v1);
      pk[t*16+u*4+2] = pack_hilo(v2);
      pk[t*16+u*4+3] = pack_hilo(v3);
    }
  }
}

__device__ __forceinline__ void epi_store_1p(const uint32_t pk[32], uint32_t* __restrict__ ebuf,
    __nv_bfloat16* __restrict__ ghi, __nv_bfloat16* __restrict__ glo,
    int row0, int tid, int wm, int wn, int gid, int tig){
  #pragma unroll
  for (int t=0;t<2;t++){
    int rA = wm*32 + t*16 + gid;
    int rB = rA + 8;
    #pragma unroll
    for (int u=0;u<4;u++){
      int cl = wn*32 + u*8 + 2*tig;
      ebuf[ cl   *LDE + rA] = pk[t*16+u*4+0];
      ebuf[(cl+1)*LDE + rA] = pk[t*16+u*4+1];
      ebuf[ cl   *LDE + rB] = pk[t*16+u*4+2];
      ebuf[(cl+1)*LDE + rB] = pk[t*16+u*4+3];
    }
  }
  __syncthreads();
  {
    int rb = tid & 15;
    int cb = tid >> 4;
    #pragma unroll
    for (int p=0;p<4;p++){
      int cl = cb + 32*p;
      #pragma unroll
      for (int h=0; h<2; h++){
        int rq = rb + 16*h;
        uint4 w = *reinterpret_cast<const uint4*>(&ebuf[cl*LDE + rq*4]);
        uint32_t hi01 = prmt_(w.x, w.y, 0x5410u);
        uint32_t hi23 = prmt_(w.z, w.w, 0x5410u);
        uint32_t lo01 = prmt_(w.x, w.y, 0x7632u);
        uint32_t lo23 = prmt_(w.z, w.w, 0x7632u);
        size_t base = (size_t)cl*NROWS + row0 + rq*4;
        *reinterpret_cast<uint2*>(&ghi[base]) = make_uint2(hi01, hi23);
        *reinterpret_cast<uint2*>(&glo[base]) = make_uint2(lo01, lo23);
      }
    }
  }
  __syncthreads();
}

__global__ __launch_bounds__(512) void proj_all_kernel(
    const float* __restrict__ act, const float* __restrict__ lng, const float* __restrict__ lnb,
    const float* __restrict__ mask,
    const float* __restrict__ Wl,  const float* __restrict__ bl,
    const float* __restrict__ Wgl, const float* __restrict__ bgl,
    const float* __restrict__ Wr,  const float* __restrict__ br,
    const float* __restrict__ Wgr, const float* __restrict__ bgr,
    const float* __restrict__ Wg,  const float* __restrict__ bg,
    __nv_bfloat16* __restrict__ gLh, __nv_bfloat16* __restrict__ gLl,
    __nv_bfloat16* __restrict__ gRh, __nv_bfloat16* __restrict__ gRl,
    float* __restrict__ gate){
  extern __shared__ uint32_t sm[];
  uint32_t* xs   = sm;
  uint32_t* w1   = sm + XS_WORDS;
  uint32_t* w2   = w1 + W_WORDS;
  int tid  = threadIdx.x;
  int row0 = blockIdx.x * 128;
  int kv   = tid & 31;

  {
    uint4 va[8];
    #pragma unroll
    for (int it=0; it<8; ++it){
      int r = (tid>>5) + it*16;
      va[it] = *reinterpret_cast<const uint4*>(&act[(size_t)(row0+r)*CDIM + kv*4]);
    }
    uint4 wA[8], wB[8];
    ldgW(Wl,  tid, wA);
    ldgW(Wgl, tid, wB);
    float4 g4 = *reinterpret_cast<const float4*>(&lng[kv*4]);
    float4 b4 = *reinterpret_cast<const float4*>(&lnb[kv*4]);
    #pragma unroll
    for (int it=0; it<8; ++it){
      int r = (tid>>5) + it*16;
      float4 v = *reinterpret_cast<const float4*>(&va[it]);
      float s  = v.x + v.y + v.z + v.w;
      float s2 = v.x*v.x + v.y*v.y + v.z*v.z + v.w*v.w;
      #pragma unroll
      for (int off=16; off>0; off>>=1){
        s  += __shfl_xor_sync(0xffffffffu, s,  off);
        s2 += __shfl_xor_sync(0xffffffffu, s2, off);
      }
      float mu = s * (1.f/128.f);
      float rs = rsqrtf(s2*(1.f/128.f) - mu*mu + EPSV);
      uint4 t;
      t.x = tf32_rna((v.x-mu)*rs*g4.x + b4.x);
      t.y = tf32_rna((v.y-mu)*rs*g4.y + b4.y);
      t.z = tf32_rna((v.z-mu)*rs*g4.z + b4.z);
      t.w = tf32_rna((v.w-mu)*rs*g4.w + b4.w);
      *reinterpret_cast<uint4*>(&xs[r*LDX + kv*4]) = t;
    }
    stsW(wA, tid, w1);
    stsW(wB, tid, w2);
  }
  __syncthreads();

  int lane = tid&31, wid = tid>>5;
  int wm = wid>>2, wn = wid&3;
  int gid = lane>>2, tig = lane&3;

  float acc1[2][4][4], acc2[2][4][4];
  uint32_t pk[32];

  // ---- GEMM 1: left (dual) ----
  #pragma unroll
  for (int t=0;t<2;t++)
    #pragma unroll
    for (int u=0;u<4;u++)
      #pragma unroll
      for (int r=0;r<4;r++){ acc1[t][u][r]=0.f; acc2[t][u][r]=0.f; }
  gemm_pair(xs, w1, w2, wm, wn, gid, tig, acc1, acc2, true);
  compute_pk(acc1, acc2, mask, bl, bgl, row0, wm, wn, gid, tig, pk);
  __syncthreads();
  {
    uint4 wA[8], wB[8];
    ldgW(Wr,  tid, wA);
    ldgW(Wgr, tid, wB);
    epi_store_1p(pk, w1, gLh, gLl, row0, tid, wm, wn, gid, tig);
    stsW(wA, tid, w1);
    stsW(wB, tid, w2);
  }
  __syncthreads();

  // ---- GEMM 2: right (dual) ----
  #pragma unroll
  for (int t=0;t<2;t++)
    #pragma unroll
    for (int u=0;u<4;u++)
      #pragma unroll
      for (int r=0;r<4;r++){ acc1[t][u][r]=0.f; acc2[t][u][r]=0.f; }
  gemm_pair(xs, w1, w2, wm, wn, gid, tig, acc1, acc2, true);
  compute_pk(acc1, acc2, mask, br, bgr, row0, wm, wn, gid, tig, pk);
  __syncthreads();
  {
    uint4 wA[8];
    ldgW(Wg, tid, wA);
    epi_store_1p(pk, w1, gRh, gRl, row0, tid, wm, wn, gid, tig);
    stsW(wA, tid, w1);
  }
  __syncthreads();

  // ---- GEMM 3: gate (single) ----
  #pragma unroll
  for (int t=0;t<2;t++)
    #pragma unroll
    for (int u=0;u<4;u++)
      #pragma unroll
      for (int r=0;r<4;r++) acc1[t][u][r]=0.f;
  gemm_pair(xs, w1, w1, wm, wn, gid, tig, acc1, acc2, false);
  #pragma unroll
  for (int t=0;t<2;t++){
    int rowA = row0 + wm*32 + t*16 + gid;
    int rowB = rowA + 8;
    #pragma unroll
    for (int u=0;u<4;u++){
      int colb = wn*32 + u*8 + 2*tig;
      float b0 = bg[colb], b1 = bg[colb+1];
      float2 oA, oB;
      oA.x = fsig(acc1[t][u][0]+b0);
      oA.y = fsig(acc1[t][u][1]+b1);
      oB.x = fsig(acc1[t][u][2]+b0);
      oB.y = fsig(acc1[t][u][3]+b1);
      *reinterpret_cast<float2*>(&gate[(size_t)rowA*CDIM + colb]) = oA;
      *reinterpret_cast<float2*>(&gate[(size_t)rowB*CDIM + colb]) = oB;
    }
  }
}

// ============== Stage 3: per-channel GEMM via bf16-split mma + ldmatrix (R13) ==============
#define TRI_LDS 72
#define TRI_SMEM ((64*TRI_LDS*2 + 128*TRI_LDS*2)*2)
__global__ __launch_bounds__(256, 2) void tri_kernel(){
  extern __shared__ __nv_bfloat16 smb[];
  __nv_bfloat16* Lhi = smb;
  __nv_bfloat16* Llo = smb + 64*TRI_LDS;
  __nv_bfloat16* Rhi = smb + 2*64*TRI_LDS;
  __nv_bfloat16* Rlo = Rhi + 128*TRI_LDS;
  uint32_t sLhi = smem_u32(Lhi);
  uint32_t sLlo = smem_u32(Llo);
  uint32_t sRhi = smem_u32(Rhi);
  uint32_t sRlo = smem_u32(Rlo);
  int tid = threadIdx.x;
  int c  = blockIdx.z;
  int i0 = blockIdx.x * 64;
  int j0 = blockIdx.y * 128;
  const __nv_bfloat16* gLh = g_Lhi + (size_t)c*NROWS;
  const __nv_bfloat16* gLl = g_Llo + (size_t)c*NROWS;
  const __nv_bfloat16* gRh = g_Rhi + (size_t)c*NROWS;
  const __nv_bfloat16* gRl = g_Rlo + (size_t)c*NROWS;

  int lane = tid&31, wid = tid>>5;
  int wm = wid>>2, wn = wid&3;
  int gid = lane>>2, tig = lane&3;

  int sr = tid>>3, sseg = tid&7;

  uint32_t offA0 = (uint32_t)(((wm*32 + (lane&15))*TRI_LDS + ((lane>>4)<<3))*2);
  uint32_t offA1 = offA0 + (uint32_t)(16*TRI_LDS*2);
  uint32_t offB0 = (uint32_t)(((wn*32 + (lane&7) + ((lane>>4)<<3))*TRI_LDS + (((lane>>3)&1)<<3))*2);
  uint32_t offB2 = offB0 + (uint32_t)(16*TRI_LDS*2);

  float acc[2][4][4];
  #pragma unroll
  for (int t=0;t<2;t++)
    #pragma unroll
    for (int u=0;u<4;u++)
      #pragma unroll
      for (int r=0;r<4;r++) acc[t][u][r]=0.f;

  for (int kc=0; kc<NTOK; kc+=64){
    __syncthreads();
    #pragma unroll
    for (int it=0; it<2; it++){
      int r = sr + it*32;
      size_t go = (size_t)(i0+r)*NTOK + kc + sseg*8;
      uint32_t so = (uint32_t)(r*TRI_LDS + sseg*8)*2;
      cp16(sLhi + so, &gLh[go]);
      cp16(sLlo + so, &gLl[go]);
    }
    #pragma unroll
    for (int it=0; it<4; it++){
      int r = sr + it*32;
      size_t go = (size_t)(j0+r)*NTOK + kc + sseg*8;
      uint32_t so = (uint32_t)(r*TRI_LDS + sseg*8)*2;
      cp16(sRhi + so, &gRh[go]);
      cp16(sRlo + so, &gRl[go]);
    }
    cp_commit_wait();
    __syncthreads();

    #pragma unroll
    for (int ks=0; ks<4; ks++){
      uint32_t kso = (uint32_t)(ks*32);
      uint32_t ah[2][4], al[2][4];
      ldm4(ah[0], sLhi + offA0 + kso);
      ldm4(ah[1], sLhi + offA1 + kso);
      ldm4(al[0], sLlo + offA0 + kso);
      ldm4(al[1], sLlo + offA1 + kso);
      uint32_t bh01[4], bh23[4], bl01[4], bl23[4];
      ldm4(bh01, sRhi + offB0 + kso);
      ldm4(bh23, sRhi + offB2 + kso);
      ldm4(bl01, sRlo + offB0 + kso);
      ldm4(bl23, sRlo + offB2 + kso);
      const uint32_t* bhp[4] = { &bh01[0], &bh01[2], &bh23[0], &bh23[2] };
      const uint32_t* blp[4] = { &bl01[0], &bl01[2], &bl23[0], &bl23[2] };
      #pragma unroll
      for (int u=0;u<4;u++){
        uint32_t bh0 = bhp[u][0], bh1 = bhp[u][1];
        uint32_t bl0 = blp[u][0], bl1 = blp[u][1];
        #pragma unroll
        for (int t=0;t<2;t++){
          mma_bf16(acc[t][u], ah[t], bh0, bh1);
          mma_bf16(acc[t][u], ah[t], bl0, bl1);
          mma_bf16(acc[t][u], al[t], bh0, bh1);
        }
      }
    }
  }

  float* To = g_tri + (size_t)c*NROWS;
  #pragma unroll
  for (int t=0;t<2;t++){
    int iA = i0 + wm*32 + t*16 + gid;
    int iB = iA + 8;
    #pragma unroll
    for (int u=0;u<4;u++){
      int j = j0 + wn*32 + u*8 + 2*tig;
      float2 vA = {acc[t][u][0], acc[t][u][1]};
      float2 vB = {acc[t][u][2], acc[t][u][3]};
      *reinterpret_cast<float2*>(&To[(size_t)iA*NTOK + j]) = vA;
      *reinterpret_cast<float2*>(&To[(size_t)iB*NTOK + j]) = vB;
    }
  }
}

// ============== Stage 4 v2: 64-row tiles, 256 threads, 2 CTAs/SM ==============
// SMEM: xs 64xLDX (fp32 staged transposed, LN'd in place to tf32) + full Wo tf32.
#define FXS_WORDS (64*LDX)
#define FINAL_SMEM ((FXS_WORDS + W_WORDS)*4)   /* (8448+17408)*4 = 103424 B */

__global__ __launch_bounds__(256, 2) void final_kernel(const float* __restrict__ cg,
                                                       const float* __restrict__ cb,
                                                       const float* __restrict__ Wo,
                                                       const float* __restrict__ bo,
                                                       float* __restrict__ out){
  extern __shared__ uint32_t sm[];
  float*    xsf = reinterpret_cast<float*>(sm);   // [ij][c], stride LDX
  uint32_t* xs  = sm;
  uint32_t* w   = sm + FXS_WORDS;
  __shared__ float p1[4][64], p2[4][64], mu_s[64], rs_s[64];
  int tid  = threadIdx.x;
  int row0 = blockIdx.x * 64;

  // stage tri tile transposed into xsf + stage Wo (tf32)
  #pragma unroll
  for (int it=0; it<8; ++it){
    int slot = tid + it*256;         // 0..2047
    int cch  = slot >> 4;            // 0..127
    int ij4  = slot & 15;            // float4 along ij
    float4 v = *reinterpret_cast<const float4*>(&g_tri[(size_t)cch*NROWS + row0 + ij4*4]);
    xsf[(ij4*4+0)*LDX + cch] = v.x;
    xsf[(ij4*4+1)*LDX + cch] = v.y;
    xsf[(ij4*4+2)*LDX + cch] = v.z;
    xsf[(ij4*4+3)*LDX + cch] = v.w;
  }
  #pragma unroll
  for (int it=0; it<16; ++it){
    int slot = tid + it*256;         // 0..4095
    int r  = slot >> 5;
    int kq = slot & 31;
    float4 v = *reinterpret_cast<const float4*>(&Wo[r*CDIM + kq*4]);
    uint4 t; t.x=tf32_rna(v.x); t.y=tf32_rna(v.y); t.z=tf32_rna(v.z); t.w=tf32_rna(v.w);
    *reinterpret_cast<uint4*>(&w[r*LDW + kq*4]) = t;
  }
  __syncthreads();

  // LN stats: 4 threads per ij row
  {
    int ij = tid & 63, pp = tid >> 6;
    float s=0.f, s2=0.f;
    #pragma unroll
    for (int k=0;k<32;k++){
      float v = xsf[ij*LDX + pp*32 + k];
      s += v; s2 += v*v;
    }
    p1[pp][ij] = s; p2[pp][ij] = s2;
  }
  __syncthreads();
  if (tid < 64){
    float s  = p1[0][tid]+p1[1][tid]+p1[2][tid]+p1[3][tid];
    float s2 = p2[0][tid]+p2[1][tid]+p2[2][tid]+p2[3][tid];
    float mu = s*(1.f/128.f);
    mu_s[tid] = mu;
    rs_s[tid] = rsqrtf(s2*(1.f/128.f) - mu*mu + EPSV);
  }
  __syncthreads();

  // normalize in place -> tf32
  {
    int ij = tid & 63, cq = tid >> 6;     // cq 0..3 -> c block of 32
    float mu = mu_s[ij], rs = rs_s[ij];
    #pragma unroll
    for (int h=0; h<8; h++){
      int c0 = cq*32 + h*4;
      float4 v = *reinterpret_cast<const float4*>(&xsf[ij*LDX + c0]);
      float4 gg = *reinterpret_cast<const float4*>(&cg[c0]);
      float4 bb = *reinterpret_cast<const float4*>(&cb[c0]);
      uint4 t;
      t.x = tf32_rna((v.x-mu)*rs*gg.x + bb.x);
      t.y = tf32_rna((v.y-mu)*rs*gg.y + bb.y);
      t.z = tf32_rna((v.z-mu)*rs*gg.z + bb.z);
      t.w = tf32_rna((v.w-mu)*rs*gg.w + bb.w);
      *reinterpret_cast<uint4*>(&xs[ij*LDX + c0]) = t;
    }
  }
  __syncthreads();

  int lane = tid&31, wid = tid>>5;
  int wm = wid>>2, wn = wid&3;          // 2 x 4 warp grid (rows 64, cols 128)
  int gid = lane>>2, tig = lane&3;

  float acc[2][4][4];
  #pragma unroll
  for (int t=0;t<2;t++)
    #pragma unroll
    for (int u=0;u<4;u++)
      #pragma unroll
      for (int r=0;r<4;r++) acc[t][u][r]=0.f;

  {
    const uint32_t* xa  = xs + (wm*32 + gid)*LDX + tig;
    const uint32_t* wb1 = w  + tig*LDW + wn*32 + gid;
    #pragma unroll
    for (int kc=0; kc<16; kc++){
      uint32_t a[2][4];
      #pragma unroll
      for (int t=0;t<2;t++){
        const uint32_t* p = xa + t*16*LDX + kc*8;
        a[t][0] = p[0];
        a[t][1] = p[8*LDX];
        a[t][2] = p[4];
        a[t][3] = p[8*LDX + 4];
      }
      #pragma unroll
      for (int u=0;u<4;u++){
        const uint32_t* q1 = wb1 + kc*8*LDW + u*8;
        uint32_t b10 = q1[0], b11 = q1[4*LDW];
        #pragma unroll
        for (int t=0;t<2;t++)
          mma_tf32(acc[t][u][0],acc[t][u][1],acc[t][u][2],acc[t][u][3],
                   a[t][0],a[t][1],a[t][2],a[t][3], b10,b11);
      }
    }
  }

  #pragma unroll
  for (int t=0;t<2;t++){
    int rowA = row0 + wm*32 + t*16 + gid;
    int rowB = rowA + 8;
    #pragma unroll
    for (int u=0;u<4;u++){
      int colb = wn*32 + u*8 + 2*tig;
      float bo0 = bo[colb], bo1 = bo[colb+1];
      float2 gA = *reinterpret_cast<const float2*>(&g_gate[(size_t)rowA*CDIM + colb]);
      float2 gB = *reinterpret_cast<const float2*>(&g_gate[(size_t)rowB*CDIM + colb]);
      float2 oA, oB;
      oA.x = (acc[t][u][0]+bo0)*gA.x;
      oA.y = (acc[t][u][1]+bo1)*gA.y;
      oB.x = (acc[t][u][2]+bo0)*gB.x;
      oB.y = (acc[t][u][3]+bo1)*gB.y;
      *reinterpret_cast<float2*>(&out[(size_t)rowA*CDIM + colb]) = oA;
      *reinterpret_cast<float2*>(&out[(size_t)rowB*CDIM + colb]) = oB;
    }
  }
}

extern "C" void kernel_launch(void* const* d_in, const int* in_sizes, int n_in,
                              void* d_out, int out_size) {
  const float* act  = (const float*)d_in[0];
  const float* mask = (const float*)d_in[1];
  const float* ln_g = (const float*)d_in[2];
  const float* ln_b = (const float*)d_in[3];
  const float* Wl   = (const float*)d_in[4];
  const float* bl   = (const float*)d_in[5];
  const float* Wr   = (const float*)d_in[6];
  const float* br   = (const float*)d_in[7];
  const float* Wgl  = (const float*)d_in[8];
  const float* bgl  = (const float*)d_in[9];
  const float* Wgr  = (const float*)d_in[10];
  const float* bgr  = (const float*)d_in[11];
  const float* cg   = (const float*)d_in[12];
  const float* cb   = (const float*)d_in[13];
  const float* Wo   = (const float*)d_in[14];
  const float* bo   = (const float*)d_in[15];
  const float* Wg   = (const float*)d_in[16];
  const float* bg   = (const float*)d_in[17];
  float* out = (float*)d_out;

  __nv_bfloat16 *dLh=nullptr, *dLl=nullptr, *dRh=nullptr, *dRl=nullptr;
  float *dGate=nullptr;
  cudaGetSymbolAddress((void**)&dLh, g_Lhi);
  cudaGetSymbolAddress((void**)&dLl, g_Llo);
  cudaGetSymbolAddress((void**)&dRh, g_Rhi);
  cudaGetSymbolAddress((void**)&dRl, g_Rlo);
  cudaGetSymbolAddress((void**)&dGate, g_gate);

  cudaFuncSetAttribute(proj_all_kernel, cudaFuncAttributeMaxDynamicSharedMemorySize, PROJALL_SMEM);
  cudaFuncSetAttribute(tri_kernel,      cudaFuncAttributeMaxDynamicSharedMemorySize, TRI_SMEM);
  cudaFuncSetAttribute(final_kernel,    cudaFuncAttributeMaxDynamicSharedMemorySize, FINAL_SMEM);

  proj_all_kernel<<<NROWS/128, 512, PROJALL_SMEM>>>(act, ln_g, ln_b, mask,
      Wl, bl, Wgl, bgl, Wr, br, Wgr, bgr, Wg, bg,
      dLh, dLl, dRh, dRl, dGate);
  tri_kernel<<<dim3(NTOK/64, NTOK/128, CDIM), 256, TRI_SMEM>>>();
  final_kernel<<<NROWS/64, 256, FINAL_SMEM>>>(cg, cb, Wo, bo, out);
}

// round 16
// speedup vs baseline: 1.6772x; 1.0125x over previous
#include <cuda_runtime.h>
#include <cuda_bf16.h>
#include <cstdint>
#include <math.h>

#define NTOK 384
#define CDIM 128
#define NROWS (NTOK*NTOK)   /* 147456 */
#define EPSV 1e-5f

// Scratch (no cudaMalloc allowed)
__device__ float g_gate[(size_t)NROWS*CDIM];
__device__ float g_tri [(size_t)NROWS*CDIM];           // [c][i*384+j]
__device__ __nv_bfloat16 g_Lhi[(size_t)CDIM*NROWS];    // [c][i*384+k]
__device__ __nv_bfloat16 g_Llo[(size_t)CDIM*NROWS];
__device__ __nv_bfloat16 g_Rhi[(size_t)CDIM*NROWS];    // [c][j*384+k]
__device__ __nv_bfloat16 g_Rlo[(size_t)CDIM*NROWS];

// fast sigmoid: MUFU.EX2 + MUFU.RCP path (rel err ~2^-21, tolerance 1e-3)
__device__ __forceinline__ float fsig(float z){
  return __fdividef(1.f, 1.f + __expf(-z));
}

__device__ __forceinline__ uint32_t tf32_rna(float f){
  uint32_t r; asm("cvt.rna.tf32.f32 %0, %1;" : "=r"(r) : "f"(f)); return r;
}
__device__ __forceinline__ uint32_t prmt_(uint32_t a, uint32_t b, uint32_t s){
  uint32_t d; asm("prmt.b32 %0,%1,%2,%3;" : "=r"(d) : "r"(a), "r"(b), "r"(s)); return d;
}
__device__ __forceinline__ uint32_t pack_hilo(float v){
  __nv_bfloat16 h = __float2bfloat16(v);
  float rem = v - __bfloat162float(h);
  __nv_bfloat16 l = __float2bfloat16(rem);
  uint16_t hb = *reinterpret_cast<uint16_t*>(&h);
  uint16_t lb = *reinterpret_cast<uint16_t*>(&l);
  return (uint32_t)hb | ((uint32_t)lb << 16);
}
__device__ __forceinline__ uint32_t smem_u32(const void* p){
  uint32_t a;
  asm("{ .reg .u64 t; cvta.to.shared.u64 t, %1; cvt.u32.u64 %0, t; }" : "=r"(a) : "l"(p));
  return a;
}
__device__ __forceinline__ void cp16(uint32_t dst_smem, const void* src){
  asm volatile("cp.async.ca.shared.global [%0], [%1], 16;" :: "r"(dst_smem), "l"(src));
}
__device__ __forceinline__ void cp_commit_wait(){
  asm volatile("cp.async.commit_group;");
  asm volatile("cp.async.wait_group 0;");
}
// ldmatrix x4 (sm_75 base ISA)
__device__ __forceinline__ void ldm4(uint32_t* r, uint32_t addr){
  asm volatile("ldmatrix.sync.aligned.m8n8.x4.shared.b16 {%0,%1,%2,%3}, [%4];"
    : "=r"(r[0]), "=r"(r[1]), "=r"(r[2]), "=r"(r[3]) : "r"(addr));
}

// m16n8k8 tf32 mma (sm_80 base ISA)
__device__ __forceinline__ void mma_tf32(float& d0, float& d1, float& d2, float& d3,
                                         uint32_t a0, uint32_t a1, uint32_t a2, uint32_t a3,
                                         uint32_t b0, uint32_t b1){
  asm volatile(
    "mma.sync.aligned.m16n8k8.row.col.f32.tf32.tf32.f32 "
    "{%0,%1,%2,%3}, {%4,%5,%6,%7}, {%8,%9}, {%0,%1,%2,%3};"
    : "+f"(d0), "+f"(d1), "+f"(d2), "+f"(d3)
    : "r"(a0), "r"(a1), "r"(a2), "r"(a3), "r"(b0), "r"(b1));
}
// m16n8k16 bf16 mma (sm_80 base ISA)
__device__ __forceinline__ void mma_bf16(float* d, const uint32_t* a, uint32_t b0, uint32_t b1){
  asm volatile(
    "mma.sync.aligned.m16n8k16.row.col.f32.bf16.bf16.f32 "
    "{%0,%1,%2,%3}, {%4,%5,%6,%7}, {%8,%9}, {%0,%1,%2,%3};"
    : "+f"(d[0]), "+f"(d[1]), "+f"(d[2]), "+f"(d[3])
    : "r"(a[0]), "r"(a[1]), "r"(a[2]), "r"(a[3]), "r"(b0), "r"(b1));
}

// ================= fused LN + 5 projections (R13 proven config) =================
#define LDX 132
#define LDW 136
#define LDE 132
#define XS_WORDS (128*LDX)
#define W_WORDS  (128*LDW)
#define PROJALL_SMEM ((XS_WORDS + 2*W_WORDS)*4)

__device__ __forceinline__ void gemm_pair(const uint32_t* __restrict__ xs,
                                          const uint32_t* __restrict__ w1,
                                          const uint32_t* __restrict__ w2,
                                          int wm, int wn, int gid, int tig,
                                          float acc1[2][4][4], float acc2[2][4][4],
                                          bool dual){
  const uint32_t* xa  = xs + (wm*32 + gid)*LDX + tig;
  const uint32_t* wb1 = w1 + tig*LDW + wn*32 + gid;
  const uint32_t* wb2 = w2 + tig*LDW + wn*32 + gid;
  #pragma unroll
  for (int kc=0; kc<16; kc++){
    uint32_t a[2][4];
    #pragma unroll
    for (int t=0;t<2;t++){
      const uint32_t* p = xa + t*16*LDX + kc*8;
      a[t][0] = p[0];
      a[t][1] = p[8*LDX];
      a[t][2] = p[4];
      a[t][3] = p[8*LDX + 4];
    }
    #pragma unroll
    for (int u=0;u<4;u++){
      const uint32_t* q1 = wb1 + kc*8*LDW + u*8;
      uint32_t b10 = q1[0], b11 = q1[4*LDW];
      #pragma unroll
      for (int t=0;t<2;t++)
        mma_tf32(acc1[t][u][0],acc1[t][u][1],acc1[t][u][2],acc1[t][u][3],
                 a[t][0],a[t][1],a[t][2],a[t][3], b10,b11);
      if (dual){
        const uint32_t* q2 = wb2 + kc*8*LDW + u*8;
        uint32_t b20 = q2[0], b21 = q2[4*LDW];
        #pragma unroll
        for (int t=0;t<2;t++)
          mma_tf32(acc2[t][u][0],acc2[t][u][1],acc2[t][u][2],acc2[t][u][3],
                   a[t][0],a[t][1],a[t][2],a[t][3], b20,b21);
      }
    }
  }
}

__device__ __forceinline__ void ldgW(const float* __restrict__ W, int tid, uint4 w[8]){
  #pragma unroll
  for (int it=0; it<8; ++it){
    int slot = tid + it*512;
    int r  = slot >> 5;
    int kv = slot & 31;
    w[it] = *reinterpret_cast<const uint4*>(&W[r*CDIM + kv*4]);
  }
}
__device__ __forceinline__ void stsW(const uint4 w[8], int tid, uint32_t* __restrict__ dst){
  #pragma unroll
  for (int it=0; it<8; ++it){
    int slot = tid + it*512;
    int r  = slot >> 5;
    int kv = slot & 31;
    float4 v = *reinterpret_cast<const float4*>(&w[it]);
    uint4 t; t.x=tf32_rna(v.x); t.y=tf32_rna(v.y); t.z=tf32_rna(v.z); t.w=tf32_rna(v.w);
    *reinterpret_cast<uint4*>(&dst[r*LDW + kv*4]) = t;
  }
}

__device__ __forceinline__ void compute_pk(const float acc1[2][4][4], const float acc2[2][4][4],
    const float* __restrict__ mask, const float* __restrict__ bb1, const float* __restrict__ bb2,
    int row0, int wm, int wn, int gid, int tig, uint32_t pk[32]){
  #pragma unroll
  for (int t=0;t<2;t++){
    int rA = wm*32 + t*16 + gid;
    int rB = rA + 8;
    float mvA = mask[row0 + rA], mvB = mask[row0 + rB];
    #pragma unroll
    for (int u=0;u<4;u++){
      int colb = wn*32 + u*8 + 2*tig;
      float2 b1v = *reinterpret_cast<const float2*>(&bb1[colb]);
      float2 b2v = *reinterpret_cast<const float2*>(&bb2[colb]);
      float v0 = mvA*(acc1[t][u][0]+b1v.x)*fsig(acc2[t][u][0]+b2v.x);
      float v1 = mvA*(acc1[t][u][1]+b1v.y)*fsig(acc2[t][u][1]+b2v.y);
      float v2 = mvB*(acc1[t][u][2]+b1v.x)*fsig(acc2[t][u][2]+b2v.x);
      float v3 = mvB*(acc1[t][u][3]+b1v.y)*fsig(acc2[t][u][3]+b2v.y);
      pk[t*16+u*4+0] = pack_hilo(v0);
      pk[t*16+u*4+1] = pack_hilo(v1);
      pk[t*16+u*4+2] = pack_hilo(v2);
      pk[t*16+u*4+3] = pack_hilo(v3);
    }
  }
}

__device__ __forceinline__ void epi_store_1p(const uint32_t pk[32], uint32_t* __restrict__ ebuf,
    __nv_bfloat16* __restrict__ ghi, __nv_bfloat16* __restrict__ glo,
    int row0, int tid, int wm, int wn, int gid, int tig){
  #pragma unroll
  for (int t=0;t<2;t++){
    int rA = wm*32 + t*16 + gid;
    int rB = rA + 8;
    #pragma unroll
    for (int u=0;u<4;u++){
      int cl = wn*32 + u*8 + 2*tig;
      ebuf[ cl   *LDE + rA] = pk[t*16+u*4+0];
      ebuf[(cl+1)*LDE + rA] = pk[t*16+u*4+1];
      ebuf[ cl   *LDE + rB] = pk[t*16+u*4+2];
      ebuf[(cl+1)*LDE + rB] = pk[t*16+u*4+3];
    }
  }
  __syncthreads();
  {
    int rb = tid & 15;
    int cb = tid >> 4;
    #pragma unroll
    for (int p=0;p<4;p++){
      int cl = cb + 32*p;
      #pragma unroll
      for (int h=0; h<2; h++){
        int rq = rb + 16*h;
        uint4 w = *reinterpret_cast<const uint4*>(&ebuf[cl*LDE + rq*4]);
        uint32_t hi01 = prmt_(w.x, w.y, 0x5410u);
        uint32_t hi23 = prmt_(w.z, w.w, 0x5410u);
        uint32_t lo01 = prmt_(w.x, w.y, 0x7632u);
        uint32_t lo23 = prmt_(w.z, w.w, 0x7632u);
        size_t base = (size_t)cl*NROWS + row0 + rq*4;
        *reinterpret_cast<uint2*>(&ghi[base]) = make_uint2(hi01, hi23);
        *reinterpret_cast<uint2*>(&glo[base]) = make_uint2(lo01, lo23);
      }
    }
  }
  __syncthreads();
}

__global__ __launch_bounds__(512) void proj_all_kernel(
    const float* __restrict__ act, const float* __restrict__ lng, const float* __restrict__ lnb,
    const float* __restrict__ mask,
    const float* __restrict__ Wl,  const float* __restrict__ bl,
    const float* __restrict__ Wgl, const float* __restrict__ bgl,
    const float* __restrict__ Wr,  const float* __restrict__ br,
    const float* __restrict__ Wgr, const float* __restrict__ bgr,
    const float* __restrict__ Wg,  const float* __restrict__ bg,
    __nv_bfloat16* __restrict__ gLh, __nv_bfloat16* __restrict__ gLl,
    __nv_bfloat16* __restrict__ gRh, __nv_bfloat16* __restrict__ gRl,
    float* __restrict__ gate){
  extern __shared__ uint32_t sm[];
  uint32_t* xs   = sm;
  uint32_t* w1   = sm + XS_WORDS;
  uint32_t* w2   = w1 + W_WORDS;
  int tid  = threadIdx.x;
  int row0 = blockIdx.x * 128;
  int kv   = tid & 31;

  {
    uint4 va[8];
    #pragma unroll
    for (int it=0; it<8; ++it){
      int r = (tid>>5) + it*16;
      va[it] = *reinterpret_cast<const uint4*>(&act[(size_t)(row0+r)*CDIM + kv*4]);
    }
    uint4 wA[8], wB[8];
    ldgW(Wl,  tid, wA);
    ldgW(Wgl, tid, wB);
    float4 g4 = *reinterpret_cast<const float4*>(&lng[kv*4]);
    float4 b4 = *reinterpret_cast<const float4*>(&lnb[kv*4]);
    #pragma unroll
    for (int it=0; it<8; ++it){
      int r = (tid>>5) + it*16;
      float4 v = *reinterpret_cast<const float4*>(&va[it]);
      float s  = v.x + v.y + v.z + v.w;
      float s2 = v.x*v.x + v.y*v.y + v.z*v.z + v.w*v.w;
      #pragma unroll
      for (int off=16; off>0; off>>=1){
        s  += __shfl_xor_sync(0xffffffffu, s,  off);
        s2 += __shfl_xor_sync(0xffffffffu, s2, off);
      }
      float mu = s * (1.f/128.f);
      float rs = rsqrtf(s2*(1.f/128.f) - mu*mu + EPSV);
      uint4 t;
      t.x = tf32_rna((v.x-mu)*rs*g4.x + b4.x);
      t.y = tf32_rna((v.y-mu)*rs*g4.y + b4.y);
      t.z = tf32_rna((v.z-mu)*rs*g4.z + b4.z);
      t.w = tf32_rna((v.w-mu)*rs*g4.w + b4.w);
      *reinterpret_cast<uint4*>(&xs[r*LDX + kv*4]) = t;
    }
    stsW(wA, tid, w1);
    stsW(wB, tid, w2);
  }
  __syncthreads();

  int lane = tid&31, wid = tid>>5;
  int wm = wid>>2, wn = wid&3;
  int gid = lane>>2, tig = lane&3;

  float acc1[2][4][4], acc2[2][4][4];
  uint32_t pk[32];

  // ---- GEMM 1: left (dual) ----
  #pragma unroll
  for (int t=0;t<2;t++)
    #pragma unroll
    for (int u=0;u<4;u++)
      #pragma unroll
      for (int r=0;r<4;r++){ acc1[t][u][r]=0.f; acc2[t][u][r]=0.f; }
  gemm_pair(xs, w1, w2, wm, wn, gid, tig, acc1, acc2, true);
  compute_pk(acc1, acc2, mask, bl, bgl, row0, wm, wn, gid, tig, pk);
  __syncthreads();
  {
    uint4 wA[8], wB[8];
    ldgW(Wr,  tid, wA);
    ldgW(Wgr, tid, wB);
    epi_store_1p(pk, w1, gLh, gLl, row0, tid, wm, wn, gid, tig);
    stsW(wA, tid, w1);
    stsW(wB, tid, w2);
  }
  __syncthreads();

  // ---- GEMM 2: right (dual) ----
  #pragma unroll
  for (int t=0;t<2;t++)
    #pragma unroll
    for (int u=0;u<4;u++)
      #pragma unroll
      for (int r=0;r<4;r++){ acc1[t][u][r]=0.f; acc2[t][u][r]=0.f; }
  gemm_pair(xs, w1, w2, wm, wn, gid, tig, acc1, acc2, true);
  compute_pk(acc1, acc2, mask, br, bgr, row0, wm, wn, gid, tig, pk);
  __syncthreads();
  {
    uint4 wA[8];
    ldgW(Wg, tid, wA);
    epi_store_1p(pk, w1, gRh, gRl, row0, tid, wm, wn, gid, tig);
    stsW(wA, tid, w1);
  }
  __syncthreads();

  // ---- GEMM 3: gate (single) ----
  #pragma unroll
  for (int t=0;t<2;t++)
    #pragma unroll
    for (int u=0;u<4;u++)
      #pragma unroll
      for (int r=0;r<4;r++) acc1[t][u][r]=0.f;
  gemm_pair(xs, w1, w1, wm, wn, gid, tig, acc1, acc2, false);
  #pragma unroll
  for (int t=0;t<2;t++){
    int rowA = row0 + wm*32 + t*16 + gid;
    int rowB = rowA + 8;
    #pragma unroll
    for (int u=0;u<4;u++){
      int colb = wn*32 + u*8 + 2*tig;
      float b0 = bg[colb], b1 = bg[colb+1];
      float2 oA, oB;
      oA.x = fsig(acc1[t][u][0]+b0);
      oA.y = fsig(acc1[t][u][1]+b1);
      oB.x = fsig(acc1[t][u][2]+b0);
      oB.y = fsig(acc1[t][u][3]+b1);
      *reinterpret_cast<float2*>(&gate[(size_t)rowA*CDIM + colb]) = oA;
      *reinterpret_cast<float2*>(&gate[(size_t)rowB*CDIM + colb]) = oB;
    }
  }
}

// ============== Stage 3: per-channel GEMM via bf16-split mma + ldmatrix (R13) ==============
#define TRI_LDS 72
#define TRI_SMEM ((64*TRI_LDS*2 + 128*TRI_LDS*2)*2)
__global__ __launch_bounds__(256, 2) void tri_kernel(){
  extern __shared__ __nv_bfloat16 smb[];
  __nv_bfloat16* Lhi = smb;
  __nv_bfloat16* Llo = smb + 64*TRI_LDS;
  __nv_bfloat16* Rhi = smb + 2*64*TRI_LDS;
  __nv_bfloat16* Rlo = Rhi + 128*TRI_LDS;
  uint32_t sLhi = smem_u32(Lhi);
  uint32_t sLlo = smem_u32(Llo);
  uint32_t sRhi = smem_u32(Rhi);
  uint32_t sRlo = smem_u32(Rlo);
  int tid = threadIdx.x;
  int c  = blockIdx.z;
  int i0 = blockIdx.x * 64;
  int j0 = blockIdx.y * 128;
  const __nv_bfloat16* gLh = g_Lhi + (size_t)c*NROWS;
  const __nv_bfloat16* gLl = g_Llo + (size_t)c*NROWS;
  const __nv_bfloat16* gRh = g_Rhi + (size_t)c*NROWS;
  const __nv_bfloat16* gRl = g_Rlo + (size_t)c*NROWS;

  int lane = tid&31, wid = tid>>5;
  int wm = wid>>2, wn = wid&3;
  int gid = lane>>2, tig = lane&3;

  int sr = tid>>3, sseg = tid&7;

  uint32_t offA0 = (uint32_t)(((wm*32 + (lane&15))*TRI_LDS + ((lane>>4)<<3))*2);
  uint32_t offA1 = offA0 + (uint32_t)(16*TRI_LDS*2);
  uint32_t offB0 = (uint32_t)(((wn*32 + (lane&7) + ((lane>>4)<<3))*TRI_LDS + (((lane>>3)&1)<<3))*2);
  uint32_t offB2 = offB0 + (uint32_t)(16*TRI_LDS*2);

  float acc[2][4][4];
  #pragma unroll
  for (int t=0;t<2;t++)
    #pragma unroll
    for (int u=0;u<4;u++)
      #pragma unroll
      for (int r=0;r<4;r++) acc[t][u][r]=0.f;

  for (int kc=0; kc<NTOK; kc+=64){
    __syncthreads();
    #pragma unroll
    for (int it=0; it<2; it++){
      int r = sr + it*32;
      size_t go = (size_t)(i0+r)*NTOK + kc + sseg*8;
      uint32_t so = (uint32_t)(r*TRI_LDS + sseg*8)*2;
      cp16(sLhi + so, &gLh[go]);
      cp16(sLlo + so, &gLl[go]);
    }
    #pragma unroll
    for (int it=0; it<4; it++){
      int r = sr + it*32;
      size_t go = (size_t)(j0+r)*NTOK + kc + sseg*8;
      uint32_t so = (uint32_t)(r*TRI_LDS + sseg*8)*2;
      cp16(sRhi + so, &gRh[go]);
      cp16(sRlo + so, &gRl[go]);
    }
    cp_commit_wait();
    __syncthreads();

    #pragma unroll
    for (int ks=0; ks<4; ks++){
      uint32_t kso = (uint32_t)(ks*32);
      uint32_t ah[2][4], al[2][4];
      ldm4(ah[0], sLhi + offA0 + kso);
      ldm4(ah[1], sLhi + offA1 + kso);
      ldm4(al[0], sLlo + offA0 + kso);
      ldm4(al[1], sLlo + offA1 + kso);
      uint32_t bh01[4], bh23[4], bl01[4], bl23[4];
      ldm4(bh01, sRhi + offB0 + kso);
      ldm4(bh23, sRhi + offB2 + kso);
      ldm4(bl01, sRlo + offB0 + kso);
      ldm4(bl23, sRlo + offB2 + kso);
      const uint32_t* bhp[4] = { &bh01[0], &bh01[2], &bh23[0], &bh23[2] };
      const uint32_t* blp[4] = { &bl01[0], &bl01[2], &bl23[0], &bl23[2] };
      #pragma unroll
      for (int u=0;u<4;u++){
        uint32_t bh0 = bhp[u][0], bh1 = bhp[u][1];
        uint32_t bl0 = blp[u][0], bl1 = blp[u][1];
        #pragma unroll
        for (int t=0;t<2;t++){
          mma_bf16(acc[t][u], ah[t], bh0, bh1);
          mma_bf16(acc[t][u], ah[t], bl0, bl1);
          mma_bf16(acc[t][u], al[t], bh0, bh1);
        }
      }
    }
  }

  float* To = g_tri + (size_t)c*NROWS;
  #pragma unroll
  for (int t=0;t<2;t++){
    int iA = i0 + wm*32 + t*16 + gid;
    int iB = iA + 8;
    #pragma unroll
    for (int u=0;u<4;u++){
      int j = j0 + wn*32 + u*8 + 2*tig;
      float2 vA = {acc[t][u][0], acc[t][u][1]};
      float2 vB = {acc[t][u][2], acc[t][u][3]};
      *reinterpret_cast<float2*>(&To[(size_t)iA*NTOK + j]) = vA;
      *reinterpret_cast<float2*>(&To[(size_t)iB*NTOK + j]) = vB;
    }
  }
}

// ============== Stage 4 v3: [c][ij] layout, no transpose, 2 CTAs/SM ==============
#define LDT2 68
#define F3XS_WORDS (128*LDT2)                    /* 8704 */
#define FINAL_SMEM ((F3XS_WORDS + W_WORDS)*4)    /* (8704+17408)*4 = 104448 B */

__global__ __launch_bounds__(256, 2) void final_kernel(const float* __restrict__ cg,
                                                       const float* __restrict__ cb,
                                                       const float* __restrict__ Wo,
                                                       const float* __restrict__ bo,
                                                       float* __restrict__ out){
  extern __shared__ uint32_t sm[];
  float*    xsf = reinterpret_cast<float*>(sm);   // [c][ij], stride LDT2
  uint32_t* xs  = sm;
  uint32_t* w   = sm + F3XS_WORDS;
  __shared__ float p1[4][64], p2[4][64], mu_s[64], rs_s[64];
  int tid  = threadIdx.x;
  int row0 = blockIdx.x * 64;

  // stage tri tile [c][ij] (coalesced float4 LDG, conflict-free float4 STS) + Wo tf32
  #pragma unroll
  for (int it=0; it<8; ++it){
    int slot = tid + it*256;          // 0..2047
    int cch  = slot >> 4;             // 0..127
    int ij4  = slot & 15;
    float4 v = *reinterpret_cast<const float4*>(&g_tri[(size_t)cch*NROWS + row0 + ij4*4]);
    *reinterpret_cast<float4*>(&xsf[cch*LDT2 + ij4*4]) = v;
  }
  #pragma unroll
  for (int it=0; it<16; ++it){
    int slot = tid + it*256;          // 0..4095
    int r  = slot >> 5;
    int kq = slot & 31;
    float4 v = *reinterpret_cast<const float4*>(&Wo[r*CDIM + kq*4]);
    uint4 t; t.x=tf32_rna(v.x); t.y=tf32_rna(v.y); t.z=tf32_rna(v.z); t.w=tf32_rna(v.w);
    *reinterpret_cast<uint4*>(&w[r*LDW + kq*4]) = t;
  }
  __syncthreads();

  // LN stats per ij: 4 threads per column
  {
    int ij = tid & 63, pp = tid >> 6;
    float s=0.f, s2=0.f;
    #pragma unroll
    for (int k=0;k<32;k++){
      float v = xsf[(pp*32+k)*LDT2 + ij];
      s += v; s2 += v*v;
    }
    p1[pp][ij] = s; p2[pp][ij] = s2;
  }
  __syncthreads();
  if (tid < 64){
    float s  = p1[0][tid]+p1[1][tid]+p1[2][tid]+p1[3][tid];
    float s2 = p2[0][tid]+p2[1][tid]+p2[2][tid]+p2[3][tid];
    float mu = s*(1.f/128.f);
    mu_s[tid] = mu;
    rs_s[tid] = rsqrtf(s2*(1.f/128.f) - mu*mu + EPSV);
  }
  __syncthreads();

  // normalize in place -> tf32 (scalar, conflict-free: bank 4c+ij rotates permutation)
  {
    int ij = tid & 63, cq = tid >> 6;
    float mu = mu_s[ij], rs = rs_s[ij];
    #pragma unroll
    for (int k=0;k<32;k++){
      int c = cq*32 + k;
      float v = xsf[c*LDT2 + ij];
      xs[c*LDT2 + ij] = tf32_rna((v-mu)*rs*cg[c] + cb[c]);
    }
  }
  __syncthreads();

  int lane = tid&31, wid = tid>>5;
  int wm = wid>>2, wn = wid&3;          // 2 x 4 warp grid (rows 64, cols 128)
  int gid = lane>>2, tig = lane&3;

  float acc[2][4][4];
  #pragma unroll
  for (int t=0;t<2;t++)
    #pragma unroll
    for (int u=0;u<4;u++)
      #pragma unroll
      for (int r=0;r<4;r++) acc[t][u][r]=0.f;

  // GEMM: A[m][k] = xs[k*LDT2 + m] — fragment loads direct from [c][ij] buffer
  {
    const uint32_t* wb1 = w + tig*LDW + wn*32 + gid;
    int rbase = wm*32 + gid;
    #pragma unroll
    for (int kc=0; kc<16; kc++){
      uint32_t a[2][4];
      #pragma unroll
      for (int t=0;t<2;t++){
        int m = rbase + t*16;
        a[t][0] = xs[(kc*8 + tig    )*LDT2 + m];
        a[t][1] = xs[(kc*8 + tig    )*LDT2 + m + 8];
        a[t][2] = xs[(kc*8 + tig + 4)*LDT2 + m];
        a[t][3] = xs[(kc*8 + tig + 4)*LDT2 + m + 8];
      }
      #pragma unroll
      for (int u=0;u<4;u++){
        const uint32_t* q1 = wb1 + kc*8*LDW + u*8;
        uint32_t b10 = q1[0], b11 = q1[4*LDW];
        #pragma unroll
        for (int t=0;t<2;t++)
          mma_tf32(acc[t][u][0],acc[t][u][1],acc[t][u][2],acc[t][u][3],
                   a[t][0],a[t][1],a[t][2],a[t][3], b10,b11);
      }
    }
  }

  #pragma unroll
  for (int t=0;t<2;t++){
    int rowA = row0 + wm*32 + t*16 + gid;
    int rowB = rowA + 8;
    #pragma unroll
    for (int u=0;u<4;u++){
      int colb = wn*32 + u*8 + 2*tig;
      float bo0 = bo[colb], bo1 = bo[colb+1];
      float2 gA = *reinterpret_cast<const float2*>(&g_gate[(size_t)rowA*CDIM + colb]);
      float2 gB = *reinterpret_cast<const float2*>(&g_gate[(size_t)rowB*CDIM + colb]);
      float2 oA, oB;
      oA.x = (acc[t][u][0]+bo0)*gA.x;
      oA.y = (acc[t][u][1]+bo1)*gA.y;
      oB.x = (acc[t][u][2]+bo0)*gB.x;
      oB.y = (acc[t][u][3]+bo1)*gB.y;
      *reinterpret_cast<float2*>(&out[(size_t)rowA*CDIM + colb]) = oA;
      *reinterpret_cast<float2*>(&out[(size_t)rowB*CDIM + colb]) = oB;
    }
  }
}

extern "C" void kernel_launch(void* const* d_in, const int* in_sizes, int n_in,
                              void* d_out, int out_size) {
  const float* act  = (const float*)d_in[0];
  const float* mask = (const float*)d_in[1];
  const float* ln_g = (const float*)d_in[2];
  const float* ln_b = (const float*)d_in[3];
  const float* Wl   = (const float*)d_in[4];
  const float* bl   = (const float*)d_in[5];
  const float* Wr   = (const float*)d_in[6];
  const float* br   = (const float*)d_in[7];
  const float* Wgl  = (const float*)d_in[8];
  const float* bgl  = (const float*)d_in[9];
  const float* Wgr  = (const float*)d_in[10];
  const float* bgr  = (const float*)d_in[11];
  const float* cg   = (const float*)d_in[12];
  const float* cb   = (const float*)d_in[13];
  const float* Wo   = (const float*)d_in[14];
  const float* bo   = (const float*)d_in[15];
  const float* Wg   = (const float*)d_in[16];
  const float* bg   = (const float*)d_in[17];
  float* out = (float*)d_out;

  __nv_bfloat16 *dLh=nullptr, *dLl=nullptr, *dRh=nullptr, *dRl=nullptr;
  float *dGate=nullptr;
  cudaGetSymbolAddress((void**)&dLh, g_Lhi);
  cudaGetSymbolAddress((void**)&dLl, g_Llo);
  cudaGetSymbolAddress((void**)&dRh, g_Rhi);
  cudaGetSymbolAddress((void**)&dRl, g_Rlo);
  cudaGetSymbolAddress((void**)&dGate, g_gate);

  cudaFuncSetAttribute(proj_all_kernel, cudaFuncAttributeMaxDynamicSharedMemorySize, PROJALL_SMEM);
  cudaFuncSetAttribute(tri_kernel,      cudaFuncAttributeMaxDynamicSharedMemorySize, TRI_SMEM);
  cudaFuncSetAttribute(final_kernel,    cudaFuncAttributeMaxDynamicSharedMemorySize, FINAL_SMEM);

  proj_all_kernel<<<NROWS/128, 512, PROJALL_SMEM>>>(act, ln_g, ln_b, mask,
      Wl, bl, Wgl, bgl, Wr, br, Wgr, bgr, Wg, bg,
      dLh, dLl, dRh, dRl, dGate);
  tri_kernel<<<dim3(NTOK/64, NTOK/128, CDIM), 256, TRI_SMEM>>>();
  final_kernel<<<NROWS/64, 256, FINAL_SMEM>>>(cg, cb, Wo, bo, out);
}

// round 17
// speedup vs baseline: 1.6847x; 1.0044x over previous
#include <cuda_runtime.h>
#include <cuda_bf16.h>
#include <cstdint>
#include <math.h>

#define NTOK 384
#define CDIM 128
#define NROWS (NTOK*NTOK)   /* 147456 */
#define EPSV 1e-5f

// Scratch (no cudaMalloc allowed)
__device__ float g_tri [(size_t)NROWS*CDIM];           // [c][i*384+j]
__device__ __nv_bfloat16 g_xh [(size_t)NROWS*CDIM];    // LN'd x, bf16, [row][c]
__device__ __nv_bfloat16 g_Lhi[(size_t)CDIM*NROWS];    // [c][i*384+k]
__device__ __nv_bfloat16 g_Llo[(size_t)CDIM*NROWS];
__device__ __nv_bfloat16 g_Rhi[(size_t)CDIM*NROWS];    // [c][j*384+k]
__device__ __nv_bfloat16 g_Rlo[(size_t)CDIM*NROWS];

// fast sigmoid: MUFU.EX2 + MUFU.RCP path (rel err ~2^-21, tolerance 1e-3)
__device__ __forceinline__ float fsig(float z){
  return __fdividef(1.f, 1.f + __expf(-z));
}

__device__ __forceinline__ uint32_t tf32_rna(float f){
  uint32_t r; asm("cvt.rna.tf32.f32 %0, %1;" : "=r"(r) : "f"(f)); return r;
}
__device__ __forceinline__ uint32_t prmt_(uint32_t a, uint32_t b, uint32_t s){
  uint32_t d; asm("prmt.b32 %0,%1,%2,%3;" : "=r"(d) : "r"(a), "r"(b), "r"(s)); return d;
}
__device__ __forceinline__ uint16_t bf16b(float v){
  __nv_bfloat16 h = __float2bfloat16(v);
  return *reinterpret_cast<uint16_t*>(&h);
}
__device__ __forceinline__ uint32_t pack_hilo(float v){
  __nv_bfloat16 h = __float2bfloat16(v);
  float rem = v - __bfloat162float(h);
  __nv_bfloat16 l = __float2bfloat16(rem);
  uint16_t hb = *reinterpret_cast<uint16_t*>(&h);
  uint16_t lb = *reinterpret_cast<uint16_t*>(&l);
  return (uint32_t)hb | ((uint32_t)lb << 16);
}
__device__ __forceinline__ uint32_t smem_u32(const void* p){
  uint32_t a;
  asm("{ .reg .u64 t; cvta.to.shared.u64 t, %1; cvt.u32.u64 %0, t; }" : "=r"(a) : "l"(p));
  return a;
}
__device__ __forceinline__ void cp16(uint32_t dst_smem, const void* src){
  asm volatile("cp.async.ca.shared.global [%0], [%1], 16;" :: "r"(dst_smem), "l"(src));
}
__device__ __forceinline__ void cp_commit_wait(){
  asm volatile("cp.async.commit_group;");
  asm volatile("cp.async.wait_group 0;");
}
// ldmatrix x4 (sm_75 base ISA)
__device__ __forceinline__ void ldm4(uint32_t* r, uint32_t addr){
  asm volatile("ldmatrix.sync.aligned.m8n8.x4.shared.b16 {%0,%1,%2,%3}, [%4];"
    : "=r"(r[0]), "=r"(r[1]), "=r"(r[2]), "=r"(r[3]) : "r"(addr));
}

// m16n8k8 tf32 mma (sm_80 base ISA)
__device__ __forceinline__ void mma_tf32(float& d0, float& d1, float& d2, float& d3,
                                         uint32_t a0, uint32_t a1, uint32_t a2, uint32_t a3,
                                         uint32_t b0, uint32_t b1){
  asm volatile(
    "mma.sync.aligned.m16n8k8.row.col.f32.tf32.tf32.f32 "
    "{%0,%1,%2,%3}, {%4,%5,%6,%7}, {%8,%9}, {%0,%1,%2,%3};"
    : "+f"(d0), "+f"(d1), "+f"(d2), "+f"(d3)
    : "r"(a0), "r"(a1), "r"(a2), "r"(a3), "r"(b0), "r"(b1));
}
// m16n8k16 bf16 mma (sm_80 base ISA)
__device__ __forceinline__ void mma_bf16(float* d, const uint32_t* a, uint32_t b0, uint32_t b1){
  asm volatile(
    "mma.sync.aligned.m16n8k16.row.col.f32.bf16.bf16.f32 "
    "{%0,%1,%2,%3}, {%4,%5,%6,%7}, {%8,%9}, {%0,%1,%2,%3};"
    : "+f"(d[0]), "+f"(d[1]), "+f"(d[2]), "+f"(d[3])
    : "r"(a[0]), "r"(a[1]), "r"(a[2]), "r"(a[3]), "r"(b0), "r"(b1));
}

// ================= fused LN + 4 projections =================
#define LDX 132
#define LDW 136
#define LDE 132
#define XS_WORDS (128*LDX)
#define W_WORDS  (128*LDW)
#define PROJALL_SMEM ((XS_WORDS + 2*W_WORDS)*4)

__device__ __forceinline__ void gemm_pair(const uint32_t* __restrict__ xs,
                                          const uint32_t* __restrict__ w1,
                                          const uint32_t* __restrict__ w2,
                                          int wm, int wn, int gid, int tig,
                                          float acc1[2][4][4], float acc2[2][4][4]){
  const uint32_t* xa  = xs + (wm*32 + gid)*LDX + tig;
  const uint32_t* wb1 = w1 + tig*LDW + wn*32 + gid;
  const uint32_t* wb2 = w2 + tig*LDW + wn*32 + gid;
  #pragma unroll
  for (int kc=0; kc<16; kc++){
    uint32_t a[2][4];
    #pragma unroll
    for (int t=0;t<2;t++){
      const uint32_t* p = xa + t*16*LDX + kc*8;
      a[t][0] = p[0];
      a[t][1] = p[8*LDX];
      a[t][2] = p[4];
      a[t][3] = p[8*LDX + 4];
    }
    #pragma unroll
    for (int u=0;u<4;u++){
      const uint32_t* q1 = wb1 + kc*8*LDW + u*8;
      uint32_t b10 = q1[0], b11 = q1[4*LDW];
      #pragma unroll
      for (int t=0;t<2;t++)
        mma_tf32(acc1[t][u][0],acc1[t][u][1],acc1[t][u][2],acc1[t][u][3],
                 a[t][0],a[t][1],a[t][2],a[t][3], b10,b11);
      const uint32_t* q2 = wb2 + kc*8*LDW + u*8;
      uint32_t b20 = q2[0], b21 = q2[4*LDW];
      #pragma unroll
      for (int t=0;t<2;t++)
        mma_tf32(acc2[t][u][0],acc2[t][u][1],acc2[t][u][2],acc2[t][u][3],
                 a[t][0],a[t][1],a[t][2],a[t][3], b20,b21);
    }
  }
}

__device__ __forceinline__ void ldgW(const float* __restrict__ W, int tid, uint4 w[8]){
  #pragma unroll
  for (int it=0; it<8; ++it){
    int slot = tid + it*512;
    int r  = slot >> 5;
    int kv = slot & 31;
    w[it] = *reinterpret_cast<const uint4*>(&W[r*CDIM + kv*4]);
  }
}
__device__ __forceinline__ void stsW(const uint4 w[8], int tid, uint32_t* __restrict__ dst){
  #pragma unroll
  for (int it=0; it<8; ++it){
    int slot = tid + it*512;
    int r  = slot >> 5;
    int kv = slot & 31;
    float4 v = *reinterpret_cast<const float4*>(&w[it]);
    uint4 t; t.x=tf32_rna(v.x); t.y=tf32_rna(v.y); t.z=tf32_rna(v.z); t.w=tf32_rna(v.w);
    *reinterpret_cast<uint4*>(&dst[r*LDW + kv*4]) = t;
  }
}

__device__ __forceinline__ void compute_pk(const float acc1[2][4][4], const float acc2[2][4][4],
    const float* __restrict__ mask, const float* __restrict__ bb1, const float* __restrict__ bb2,
    int row0, int wm, int wn, int gid, int tig, uint32_t pk[32]){
  #pragma unroll
  for (int t=0;t<2;t++){
    int rA = wm*32 + t*16 + gid;
    int rB = rA + 8;
    float mvA = mask[row0 + rA], mvB = mask[row0 + rB];
    #pragma unroll
    for (int u=0;u<4;u++){
      int colb = wn*32 + u*8 + 2*tig;
      float2 b1v = *reinterpret_cast<const float2*>(&bb1[colb]);
      float2 b2v = *reinterpret_cast<const float2*>(&bb2[colb]);
      float v0 = mvA*(acc1[t][u][0]+b1v.x)*fsig(acc2[t][u][0]+b2v.x);
      float v1 = mvA*(acc1[t][u][1]+b1v.y)*fsig(acc2[t][u][1]+b2v.y);
      float v2 = mvB*(acc1[t][u][2]+b1v.x)*fsig(acc2[t][u][2]+b2v.x);
      float v3 = mvB*(acc1[t][u][3]+b1v.y)*fsig(acc2[t][u][3]+b2v.y);
      pk[t*16+u*4+0] = pack_hilo(v0);
      pk[t*16+u*4+1] = pack_hilo(v1);
      pk[t*16+u*4+2] = pack_hilo(v2);
      pk[t*16+u*4+3] = pack_hilo(v3);
    }
  }
}

__device__ __forceinline__ void epi_store_1p(const uint32_t pk[32], uint32_t* __restrict__ ebuf,
    __nv_bfloat16* __restrict__ ghi, __nv_bfloat16* __restrict__ glo,
    int row0, int tid, int wm, int wn, int gid, int tig){
  #pragma unroll
  for (int t=0;t<2;t++){
    int rA = wm*32 + t*16 + gid;
    int rB = rA + 8;
    #pragma unroll
    for (int u=0;u<4;u++){
      int cl = wn*32 + u*8 + 2*tig;
      ebuf[ cl   *LDE + rA] = pk[t*16+u*4+0];
      ebuf[(cl+1)*LDE + rA] = pk[t*16+u*4+1];
      ebuf[ cl   *LDE + rB] = pk[t*16+u*4+2];
      ebuf[(cl+1)*LDE + rB] = pk[t*16+u*4+3];
    }
  }
  __syncthreads();
  {
    int rb = tid & 15;
    int cb = tid >> 4;
    #pragma unroll
    for (int p=0;p<4;p++){
      int cl = cb + 32*p;
      #pragma unroll
      for (int h=0; h<2; h++){
        int rq = rb + 16*h;
        uint4 w = *reinterpret_cast<const uint4*>(&ebuf[cl*LDE + rq*4]);
        uint32_t hi01 = prmt_(w.x, w.y, 0x5410u);
        uint32_t hi23 = prmt_(w.z, w.w, 0x5410u);
        uint32_t lo01 = prmt_(w.x, w.y, 0x7632u);
        uint32_t lo23 = prmt_(w.z, w.w, 0x7632u);
        size_t base = (size_t)cl*NROWS + row0 + rq*4;
        *reinterpret_cast<uint2*>(&ghi[base]) = make_uint2(hi01, hi23);
        *reinterpret_cast<uint2*>(&glo[base]) = make_uint2(lo01, lo23);
      }
    }
  }
  __syncthreads();
}

__global__ __launch_bounds__(512) void proj_all_kernel(
    const float* __restrict__ act, const float* __restrict__ lng, const float* __restrict__ lnb,
    const float* __restrict__ mask,
    const float* __restrict__ Wl,  const float* __restrict__ bl,
    const float* __restrict__ Wgl, const float* __restrict__ bgl,
    const float* __restrict__ Wr,  const float* __restrict__ br,
    const float* __restrict__ Wgr, const float* __restrict__ bgr,
    __nv_bfloat16* __restrict__ gLh, __nv_bfloat16* __restrict__ gLl,
    __nv_bfloat16* __restrict__ gRh, __nv_bfloat16* __restrict__ gRl,
    __nv_bfloat16* __restrict__ xh){
  extern __shared__ uint32_t sm[];
  uint32_t* xs   = sm;
  uint32_t* w1   = sm + XS_WORDS;
  uint32_t* w2   = w1 + W_WORDS;
  int tid  = threadIdx.x;
  int row0 = blockIdx.x * 128;
  int kv   = tid & 31;

  // ---- staging: act LDG + in-register LN + tf32 STS + bf16 xln store ----
  {
    uint4 va[8];
    #pragma unroll
    for (int it=0; it<8; ++it){
      int r = (tid>>5) + it*16;
      va[it] = *reinterpret_cast<const uint4*>(&act[(size_t)(row0+r)*CDIM + kv*4]);
    }
    uint4 wA[8], wB[8];
    ldgW(Wl,  tid, wA);
    ldgW(Wgl, tid, wB);
    float4 g4 = *reinterpret_cast<const float4*>(&lng[kv*4]);
    float4 b4 = *reinterpret_cast<const float4*>(&lnb[kv*4]);
    #pragma unroll
    for (int it=0; it<8; ++it){
      int r = (tid>>5) + it*16;
      float4 v = *reinterpret_cast<const float4*>(&va[it]);
      float s  = v.x + v.y + v.z + v.w;
      float s2 = v.x*v.x + v.y*v.y + v.z*v.z + v.w*v.w;
      #pragma unroll
      for (int off=16; off>0; off>>=1){
        s  += __shfl_xor_sync(0xffffffffu, s,  off);
        s2 += __shfl_xor_sync(0xffffffffu, s2, off);
      }
      float mu = s * (1.f/128.f);
      float rs = rsqrtf(s2*(1.f/128.f) - mu*mu + EPSV);
      float l0 = (v.x-mu)*rs*g4.x + b4.x;
      float l1 = (v.y-mu)*rs*g4.y + b4.y;
      float l2 = (v.z-mu)*rs*g4.z + b4.z;
      float l3 = (v.w-mu)*rs*g4.w + b4.w;
      uint4 t; t.x=tf32_rna(l0); t.y=tf32_rna(l1); t.z=tf32_rna(l2); t.w=tf32_rna(l3);
      *reinterpret_cast<uint4*>(&xs[r*LDX + kv*4]) = t;
      uint32_t pa = (uint32_t)bf16b(l0) | ((uint32_t)bf16b(l1)<<16);
      uint32_t pb = (uint32_t)bf16b(l2) | ((uint32_t)bf16b(l3)<<16);
      *reinterpret_cast<uint2*>(&xh[(size_t)(row0+r)*CDIM + kv*4]) = make_uint2(pa, pb);
    }
    stsW(wA, tid, w1);
    stsW(wB, tid, w2);
  }
  __syncthreads();

  int lane = tid&31, wid = tid>>5;
  int wm = wid>>2, wn = wid&3;
  int gid = lane>>2, tig = lane&3;

  float acc1[2][4][4], acc2[2][4][4];
  uint32_t pk[32];

  // ---- GEMM 1: left ----
  #pragma unroll
  for (int t=0;t<2;t++)
    #pragma unroll
    for (int u=0;u<4;u++)
      #pragma unroll
      for (int r=0;r<4;r++){ acc1[t][u][r]=0.f; acc2[t][u][r]=0.f; }
  gemm_pair(xs, w1, w2, wm, wn, gid, tig, acc1, acc2);
  compute_pk(acc1, acc2, mask, bl, bgl, row0, wm, wn, gid, tig, pk);
  __syncthreads();
  {
    uint4 wA[8], wB[8];
    ldgW(Wr,  tid, wA);
    ldgW(Wgr, tid, wB);
    epi_store_1p(pk, w1, gLh, gLl, row0, tid, wm, wn, gid, tig);
    stsW(wA, tid, w1);
    stsW(wB, tid, w2);
  }
  __syncthreads();

  // ---- GEMM 2: right ----
  #pragma unroll
  for (int t=0;t<2;t++)
    #pragma unroll
    for (int u=0;u<4;u++)
      #pragma unroll
      for (int r=0;r<4;r++){ acc1[t][u][r]=0.f; acc2[t][u][r]=0.f; }
  gemm_pair(xs, w1, w2, wm, wn, gid, tig, acc1, acc2);
  compute_pk(acc1, acc2, mask, br, bgr, row0, wm, wn, gid, tig, pk);
  __syncthreads();
  epi_store_1p(pk, w1, gRh, gRl, row0, tid, wm, wn, gid, tig);
}

// ============== Stage 3: per-channel GEMM via bf16-split mma + ldmatrix (R13) ==============
#define TRI_LDS 72
#define TRI_SMEM ((64*TRI_LDS*2 + 128*TRI_LDS*2)*2)
__global__ __launch_bounds__(256, 2) void tri_kernel(){
  extern __shared__ __nv_bfloat16 smb[];
  __nv_bfloat16* Lhi = smb;
  __nv_bfloat16* Llo = smb + 64*TRI_LDS;
  __nv_bfloat16* Rhi = smb + 2*64*TRI_LDS;
  __nv_bfloat16* Rlo = Rhi + 128*TRI_LDS;
  uint32_t sLhi = smem_u32(Lhi);
  uint32_t sLlo = smem_u32(Llo);
  uint32_t sRhi = smem_u32(Rhi);
  uint32_t sRlo = smem_u32(Rlo);
  int tid = threadIdx.x;
  int c  = blockIdx.z;
  int i0 = blockIdx.x * 64;
  int j0 = blockIdx.y * 128;
  const __nv_bfloat16* gLh = g_Lhi + (size_t)c*NROWS;
  const __nv_bfloat16* gLl = g_Llo + (size_t)c*NROWS;
  const __nv_bfloat16* gRh = g_Rhi + (size_t)c*NROWS;
  const __nv_bfloat16* gRl = g_Rlo + (size_t)c*NROWS;

  int lane = tid&31, wid = tid>>5;
  int wm = wid>>2, wn = wid&3;
  int gid = lane>>2, tig = lane&3;

  int sr = tid>>3, sseg = tid&7;

  uint32_t offA0 = (uint32_t)(((wm*32 + (lane&15))*TRI_LDS + ((lane>>4)<<3))*2);
  uint32_t offA1 = offA0 + (uint32_t)(16*TRI_LDS*2);
  uint32_t offB0 = (uint32_t)(((wn*32 + (lane&7) + ((lane>>4)<<3))*TRI_LDS + (((lane>>3)&1)<<3))*2);
  uint32_t offB2 = offB0 + (uint32_t)(16*TRI_LDS*2);

  float acc[2][4][4];
  #pragma unroll
  for (int t=0;t<2;t++)
    #pragma unroll
    for (int u=0;u<4;u++)
      #pragma unroll
      for (int r=0;r<4;r++) acc[t][u][r]=0.f;

  for (int kc=0; kc<NTOK; kc+=64){
    __syncthreads();
    #pragma unroll
    for (int it=0; it<2; it++){
      int r = sr + it*32;
      size_t go = (size_t)(i0+r)*NTOK + kc + sseg*8;
      uint32_t so = (uint32_t)(r*TRI_LDS + sseg*8)*2;
      cp16(sLhi + so, &gLh[go]);
      cp16(sLlo + so, &gLl[go]);
    }
    #pragma unroll
    for (int it=0; it<4; it++){
      int r = sr + it*32;
      size_t go = (size_t)(j0+r)*NTOK + kc + sseg*8;
      uint32_t so = (uint32_t)(r*TRI_LDS + sseg*8)*2;
      cp16(sRhi + so, &gRh[go]);
      cp16(sRlo + so, &gRl[go]);
    }
    cp_commit_wait();
    __syncthreads();

    #pragma unroll
    for (int ks=0; ks<4; ks++){
      uint32_t kso = (uint32_t)(ks*32);
      uint32_t ah[2][4], al[2][4];
      ldm4(ah[0], sLhi + offA0 + kso);
      ldm4(ah[1], sLhi + offA1 + kso);
      ldm4(al[0], sLlo + offA0 + kso);
      ldm4(al[1], sLlo + offA1 + kso);
      uint32_t bh01[4], bh23[4], bl01[4], bl23[4];
      ldm4(bh01, sRhi + offB0 + kso);
      ldm4(bh23, sRhi + offB2 + kso);
      ldm4(bl01, sRlo + offB0 + kso);
      ldm4(bl23, sRlo + offB2 + kso);
      const uint32_t* bhp[4] = { &bh01[0], &bh01[2], &bh23[0], &bh23[2] };
      const uint32_t* blp[4] = { &bl01[0], &bl01[2], &bl23[0], &bl23[2] };
      #pragma unroll
      for (int u=0;u<4;u++){
        uint32_t bh0 = bhp[u][0], bh1 = bhp[u][1];
        uint32_t bl0 = blp[u][0], bl1 = blp[u][1];
        #pragma unroll
        for (int t=0;t<2;t++){
          mma_bf16(acc[t][u], ah[t], bh0, bh1);
          mma_bf16(acc[t][u], ah[t], bl0, bl1);
          mma_bf16(acc[t][u], al[t], bh0, bh1);
        }
      }
    }
  }

  float* To = g_tri + (size_t)c*NROWS;
  #pragma unroll
  for (int t=0;t<2;t++){
    int iA = i0 + wm*32 + t*16 + gid;
    int iB = iA + 8;
    #pragma unroll
    for (int u=0;u<4;u++){
      int j = j0 + wn*32 + u*8 + 2*tig;
      float2 vA = {acc[t][u][0], acc[t][u][1]};
      float2 vB = {acc[t][u][2], acc[t][u][3]};
      *reinterpret_cast<float2*>(&To[(size_t)iA*NTOK + j]) = vA;
      *reinterpret_cast<float2*>(&To[(size_t)iB*NTOK + j]) = vB;
    }
  }
}

// ============== Stage 4: LN(tri)@Wo + gate-GEMM(xln@Wg) fused ==============
__device__ __forceinline__ void gemm_full(const uint32_t* __restrict__ xs,
                                          const uint32_t* __restrict__ w1,
                                          int wm, int wn, int gid, int tig,
                                          float acc1[2][4][4]){
  const uint32_t* xa  = xs + (wm*32 + gid)*LDX + tig;
  const uint32_t* wb1 = w1 + tig*LDW + wn*32 + gid;
  #pragma unroll
  for (int kc=0; kc<16; kc++){
    uint32_t a[2][4];
    #pragma unroll
    for (int t=0;t<2;t++){
      const uint32_t* p = xa + t*16*LDX + kc*8;
      a[t][0] = p[0];
      a[t][1] = p[8*LDX];
      a[t][2] = p[4];
      a[t][3] = p[8*LDX + 4];
    }
    #pragma unroll
    for (int u=0;u<4;u++){
      const uint32_t* q1 = wb1 + kc*8*LDW + u*8;
      uint32_t b10 = q1[0], b11 = q1[4*LDW];
      #pragma unroll
      for (int t=0;t<2;t++)
        mma_tf32(acc1[t][u][0],acc1[t][u][1],acc1[t][u][2],acc1[t][u][3],
                 a[t][0],a[t][1],a[t][2],a[t][3], b10,b11);
    }
  }
}

#define LDT 129
#define FINAL_SMEM ((128*LDT + XS_WORDS + W_WORDS)*4)
__global__ __launch_bounds__(512) void final_kernel(const float* __restrict__ cg,
                                                    const float* __restrict__ cb,
                                                    const float* __restrict__ Wo,
                                                    const float* __restrict__ bo,
                                                    const float* __restrict__ Wg,
                                                    const float* __restrict__ bg,
                                                    float* __restrict__ out){
  extern __shared__ uint32_t sm[];
  float*    T  = reinterpret_cast<float*>(sm);
  uint32_t* xs = sm + 128*LDT;
  uint32_t* w  = xs + XS_WORDS;
  __shared__ float p1[4][128], p2[4][128], mu_s[128], rs_s[128];
  int tid  = threadIdx.x;
  int row0 = blockIdx.x * 128;

  // stage tri tile + Wo (tf32)
  #pragma unroll
  for (int it=0; it<8; ++it){
    int slot = tid + it*512;
    int cch = slot >> 5;
    int v4  = slot & 31;
    float4 v = *reinterpret_cast<const float4*>(&g_tri[(size_t)cch*NROWS + row0 + v4*4]);
    T[cch*LDT + v4*4 + 0] = v.x;
    T[cch*LDT + v4*4 + 1] = v.y;
    T[cch*LDT + v4*4 + 2] = v.z;
    T[cch*LDT + v4*4 + 3] = v.w;
    v = *reinterpret_cast<const float4*>(&Wo[cch*CDIM + v4*4]);
    uint4 t; t.x=tf32_rna(v.x); t.y=tf32_rna(v.y); t.z=tf32_rna(v.z); t.w=tf32_rna(v.w);
    *reinterpret_cast<uint4*>(&w[cch*LDW + v4*4]) = t;
  }
  __syncthreads();

  {
    int ij = tid & 127, pp = tid >> 7;
    float s=0.f, s2=0.f;
    #pragma unroll
    for (int k=0;k<32;k++){
      float v = T[(pp*32+k)*LDT + ij];
      s += v; s2 += v*v;
    }
    p1[pp][ij] = s; p2[pp][ij] = s2;
  }
  __syncthreads();
  if (tid < 128){
    float s  = p1[0][tid]+p1[1][tid]+p1[2][tid]+p1[3][tid];
    float s2 = p2[0][tid]+p2[1][tid]+p2[2][tid]+p2[3][tid];
    float mu = s*(1.f/128.f);
    mu_s[tid] = mu;
    rs_s[tid] = rsqrtf(s2*(1.f/128.f) - mu*mu + EPSV);
  }
  __syncthreads();

  #pragma unroll
  for (int it=0; it<8; ++it){
    int slot = tid + it*512;
    int r  = slot & 127;
    int cq = slot >> 7;
    float mu = mu_s[r], rs = rs_s[r];
    uint4 t;
    {
      int c0 = cq*4;
      float v0 = (T[(c0+0)*LDT + r]-mu)*rs*cg[c0+0] + cb[c0+0];
      float v1 = (T[(c0+1)*LDT + r]-mu)*rs*cg[c0+1] + cb[c0+1];
      float v2 = (T[(c0+2)*LDT + r]-mu)*rs*cg[c0+2] + cb[c0+2];
      float v3 = (T[(c0+3)*LDT + r]-mu)*rs*cg[c0+3] + cb[c0+3];
      t.x=tf32_rna(v0); t.y=tf32_rna(v1); t.z=tf32_rna(v2); t.w=tf32_rna(v3);
    }
    *reinterpret_cast<uint4*>(&xs[r*LDX + cq*4]) = t;
  }
  __syncthreads();

  int lane = tid&31, wid = tid>>5;
  int wm = wid>>2, wn = wid&3;
  int gid = lane>>2, tig = lane&3;

  float acc1[2][4][4], acc2[2][4][4];
  #pragma unroll
  for (int t=0;t<2;t++)
    #pragma unroll
    for (int u=0;u<4;u++)
      #pragma unroll
      for (int r=0;r<4;r++){ acc1[t][u][r]=0.f; acc2[t][u][r]=0.f; }

  // GEMM 1: LN(tri) @ Wo
  gemm_full(xs, w, wm, wn, gid, tig, acc1);
  __syncthreads();

  // restage: xln (bf16 -> tf32 via <<16 / mask) and Wg (tf32)
  #pragma unroll
  for (int it=0; it<8; ++it){
    int slot = tid + it*512;
    int r  = slot >> 5;
    int kv = slot & 31;
    uint2 hv = *reinterpret_cast<const uint2*>(&g_xh[(size_t)(row0+r)*CDIM + kv*4]);
    uint4 t;
    t.x = hv.x << 16;
    t.y = hv.x & 0xFFFF0000u;
    t.z = hv.y << 16;
    t.w = hv.y & 0xFFFF0000u;
    *reinterpret_cast<uint4*>(&xs[r*LDX + kv*4]) = t;
    float4 v = *reinterpret_cast<const float4*>(&Wg[r*CDIM + kv*4]);
    uint4 tw; tw.x=tf32_rna(v.x); tw.y=tf32_rna(v.y); tw.z=tf32_rna(v.z); tw.w=tf32_rna(v.w);
    *reinterpret_cast<uint4*>(&w[r*LDW + kv*4]) = tw;
  }
  __syncthreads();

  // GEMM 2: xln @ Wg
  gemm_full(xs, w, wm, wn, gid, tig, acc2);

  #pragma unroll
  for (int t=0;t<2;t++){
    int rowA = row0 + wm*32 + t*16 + gid;
    int rowB = rowA + 8;
    #pragma unroll
    for (int u=0;u<4;u++){
      int colb = wn*32 + u*8 + 2*tig;
      float bo0 = bo[colb], bo1 = bo[colb+1];
      float bg0 = bg[colb], bg1 = bg[colb+1];
      float2 oA, oB;
      oA.x = (acc1[t][u][0]+bo0)*fsig(acc2[t][u][0]+bg0);
      oA.y = (acc1[t][u][1]+bo1)*fsig(acc2[t][u][1]+bg1);
      oB.x = (acc1[t][u][2]+bo0)*fsig(acc2[t][u][2]+bg0);
      oB.y = (acc1[t][u][3]+bo1)*fsig(acc2[t][u][3]+bg1);
      *reinterpret_cast<float2*>(&out[(size_t)rowA*CDIM + colb]) = oA;
      *reinterpret_cast<float2*>(&out[(size_t)rowB*CDIM + colb]) = oB;
    }
  }
}

extern "C" void kernel_launch(void* const* d_in, const int* in_sizes, int n_in,
                              void* d_out, int out_size) {
  const float* act  = (const float*)d_in[0];
  const float* mask = (const float*)d_in[1];
  const float* ln_g = (const float*)d_in[2];
  const float* ln_b = (const float*)d_in[3];
  const float* Wl   = (const float*)d_in[4];
  const float* bl   = (const float*)d_in[5];
  const float* Wr   = (const float*)d_in[6];
  const float* br   = (const float*)d_in[7];
  const float* Wgl  = (const float*)d_in[8];
  const float* bgl  = (const float*)d_in[9];
  const float* Wgr  = (const float*)d_in[10];
  const float* bgr  = (const float*)d_in[11];
  const float* cg   = (const float*)d_in[12];
  const float* cb   = (const float*)d_in[13];
  const float* Wo   = (const float*)d_in[14];
  const float* bo   = (const float*)d_in[15];
  const float* Wg   = (const float*)d_in[16];
  const float* bg   = (const float*)d_in[17];
  float* out = (float*)d_out;

  __nv_bfloat16 *dLh=nullptr, *dLl=nullptr, *dRh=nullptr, *dRl=nullptr, *dXh=nullptr;
  cudaGetSymbolAddress((void**)&dLh, g_Lhi);
  cudaGetSymbolAddress((void**)&dLl, g_Llo);
  cudaGetSymbolAddress((void**)&dRh, g_Rhi);
  cudaGetSymbolAddress((void**)&dRl, g_Rlo);
  cudaGetSymbolAddress((void**)&dXh, g_xh);

  cudaFuncSetAttribute(proj_all_kernel, cudaFuncAttributeMaxDynamicSharedMemorySize, PROJALL_SMEM);
  cudaFuncSetAttribute(tri_kernel,      cudaFuncAttributeMaxDynamicSharedMemorySize, TRI_SMEM);
  cudaFuncSetAttribute(final_kernel,    cudaFuncAttributeMaxDynamicSharedMemorySize, FINAL_SMEM);

  proj_all_kernel<<<NROWS/128, 512, PROJALL_SMEM>>>(act, ln_g, ln_b, mask,
      Wl, bl, Wgl, bgl, Wr, br, Wgr, bgr,
      dLh, dLl, dRh, dRl, dXh);
  tri_kernel<<<dim3(NTOK/64, NTOK/128, CDIM), 256, TRI_SMEM>>>();
  final_kernel<<<NROWS/128, 512, FINAL_SMEM>>>(cg, cb, Wo, bo, Wg, bg, out);
}